// round 2
// baseline (speedup 1.0000x reference)
#include <cuda_runtime.h>
#include <cuda_bf16.h>
#include <cstdint>

// Problem constants
#define B 4
#define S 1024
#define D 1024
#define H 16
#define DK 64
#define L 2047          // 2*S - 1
#define BS (B*S)        // 4096

// ---------------------------------------------------------------------------
// Scratch (static device globals; no runtime allocation allowed)
// ---------------------------------------------------------------------------
__device__ float g_Q [BS * D];
__device__ float g_K [BS * D];
__device__ float g_V [BS * D];
__device__ float g_KR[BS * D];
__device__ float g_P [L * D];
__device__ float g_PR[L * D];
__device__ float g_ub[B * H * S];
__device__ float g_Bv[H * L];
__device__ float g_VW[BS * D];

// ---------------------------------------------------------------------------
// GEMM: C[M,N] = A[M,K] @ W[N,K]^T + bias[N]
// 128x128 block, K-tile 8, 256 threads, 8x8 microtile.
// N and K are always multiples of 128/8 here; only M needs guarding (M=2047).
// ---------------------------------------------------------------------------
__global__ __launch_bounds__(256) void gemm_bias(
    const float* __restrict__ A, const float* __restrict__ W,
    const float* __restrict__ bias, float* __restrict__ C,
    int M, int N, int K)
{
    __shared__ float As[8][132];
    __shared__ float Ws[8][132];

    const int tid = threadIdx.x;
    const int bm = blockIdx.y * 128;
    const int bn = blockIdx.x * 128;
    const int tx = tid & 15;      // 0..15 (n microtile)
    const int ty = tid >> 4;      // 0..15 (m microtile)
    const int lrow = tid >> 1;    // 0..127
    const int lcol = (tid & 1) << 2;

    float acc[8][8];
#pragma unroll
    for (int i = 0; i < 8; i++)
#pragma unroll
        for (int j = 0; j < 8; j++) acc[i][j] = 0.0f;

    const bool avalid = (bm + lrow) < M;
    const float* Ap = A + (size_t)(bm + lrow) * K + lcol;
    const float* Wp = W + (size_t)(bn + lrow) * K + lcol;

    for (int k0 = 0; k0 < K; k0 += 8) {
        float4 av = avalid ? *(const float4*)(Ap + k0) : make_float4(0.f, 0.f, 0.f, 0.f);
        float4 wv = *(const float4*)(Wp + k0);
        As[lcol + 0][lrow] = av.x; As[lcol + 1][lrow] = av.y;
        As[lcol + 2][lrow] = av.z; As[lcol + 3][lrow] = av.w;
        Ws[lcol + 0][lrow] = wv.x; Ws[lcol + 1][lrow] = wv.y;
        Ws[lcol + 2][lrow] = wv.z; Ws[lcol + 3][lrow] = wv.w;
        __syncthreads();

#pragma unroll
        for (int kk = 0; kk < 8; kk++) {
            float a[8], bb[8];
            *(float4*)&a[0]  = *(const float4*)&As[kk][ty * 8];
            *(float4*)&a[4]  = *(const float4*)&As[kk][ty * 8 + 4];
            *(float4*)&bb[0] = *(const float4*)&Ws[kk][tx * 8];
            *(float4*)&bb[4] = *(const float4*)&Ws[kk][tx * 8 + 4];
#pragma unroll
            for (int i = 0; i < 8; i++)
#pragma unroll
                for (int j = 0; j < 8; j++)
                    acc[i][j] = fmaf(a[i], bb[j], acc[i][j]);
        }
        __syncthreads();
    }

    float bj[8];
#pragma unroll
    for (int j = 0; j < 8; j++) bj[j] = bias[bn + tx * 8 + j];

#pragma unroll
    for (int i = 0; i < 8; i++) {
        int gm = bm + ty * 8 + i;
        if (gm < M) {
            float* Cp = C + (size_t)gm * N + bn + tx * 8;
#pragma unroll
            for (int j = 0; j < 8; j++) Cp[j] = acc[i][j] + bj[j];
        }
    }
}

// ---------------------------------------------------------------------------
// ubias[b,h,z] = sum_d rel_u[h,d] * KR[b,z,h,d]
// ---------------------------------------------------------------------------
__global__ void ubias_kernel(const float* __restrict__ KR,
                             const float* __restrict__ rel_u,
                             float* __restrict__ ub)
{
    int idx = blockIdx.x * 256 + threadIdx.x;   // b*16384 + h*1024 + z
    if (idx >= B * H * S) return;
    int z = idx & (S - 1);
    int h = (idx >> 10) & (H - 1);
    int b = idx >> 14;
    const float* kr = KR + ((size_t)(b * S + z)) * D + h * DK;
    const float* ru = rel_u + h * DK;
    float s = 0.f;
#pragma unroll
    for (int d = 0; d < DK; d++) s = fmaf(kr[d], ru[d], s);
    ub[idx] = s;
}

// ---------------------------------------------------------------------------
// Bv[h,l] = sum_d rel_v[h,d] * PR[l,h,d]
// ---------------------------------------------------------------------------
__global__ void bv_kernel(const float* __restrict__ PR,
                          const float* __restrict__ rel_v,
                          float* __restrict__ Bv)
{
    int idx = blockIdx.x * 256 + threadIdx.x;
    if (idx >= H * L) return;
    int l = idx % L;
    int h = idx / L;
    const float* pr = PR + (size_t)l * D + h * DK;
    const float* rv = rel_v + h * DK;
    float s = 0.f;
#pragma unroll
    for (int d = 0; d < DK; d++) s = fmaf(pr[d], rv[d], s);
    Bv[h * L + l] = s;
}

// ---------------------------------------------------------------------------
// Fused relative attention (flash-style, causal).
// Grid: (S/64 s-tiles, B*H). Block: 256 threads. Each CTA handles 64 q-rows.
// Thread layout: r = tid/4 (q-row), c4 = tid%4 (j-stripe & 16-wide d-stripe).
// logits = (q.k + q.P[j-i+1023] + ubias[z] + Bv[j-i+1023]) / 8, causal mask,
// online softmax, O += p * V.
// ---------------------------------------------------------------------------
#define ATTN_SMEM_FLOATS (64*65 + 64*65 + 64*68 + 127*65 + 64*65 + 64 + 128)

__global__ __launch_bounds__(256) void attn_kernel(
    const float* __restrict__ Q, const float* __restrict__ K,
    const float* __restrict__ V, const float* __restrict__ P,
    const float* __restrict__ ubias, const float* __restrict__ Bv,
    float* __restrict__ O)
{
    const int st = blockIdx.x;
    const int b  = blockIdx.y >> 4;
    const int h  = blockIdx.y & 15;
    const int tid = threadIdx.x;
    const int r  = tid >> 2;
    const int c4 = tid & 3;
    const int s0 = st * 64;

    extern __shared__ float sm[];
    float* Qs  = sm;                 // 64 x (stride 65)
    float* Ks  = Qs + 64 * 65;       // 64 x 65
    float* Vs  = Ks + 64 * 65;       // 64 x (stride 68, keeps float4 align)
    float* Ps  = Vs + 64 * 68;       // 127 x 65
    float* Pr  = Ps + 127 * 65;      // 64 x 65 (probabilities)
    float* ub  = Pr + 64 * 65;       // 64
    float* bvs = ub + 64;            // 127 (+1 pad)

    const float* Qg = Q + ((size_t)(b * S + s0)) * D + h * DK;
    for (int e = tid; e < 64 * 64; e += 256) {
        int i = e >> 6, d = e & 63;
        Qs[i * 65 + d] = Qg[(size_t)i * D + d];
    }

    float Ob[16];
#pragma unroll
    for (int d = 0; d < 16; d++) Ob[d] = 0.f;
    float mrow = -1e30f, lrow = 0.f;

    const int prow = 63 - r;   // local P-row offset for this q-row

    for (int zt = 0; zt <= st; zt++) {
        const int z0 = zt * 64;
        const int lbase = (zt - st) * 64 + 960;   // >= 0, +126 <= 1086 < 2047

        __syncthreads();   // protect Ks/Vs/Ps/Pr from previous iteration

        const float* Kg = K + ((size_t)(b * S + z0)) * D + h * DK;
        const float* Vg = V + ((size_t)(b * S + z0)) * D + h * DK;
        for (int e = tid; e < 64 * 64; e += 256) {
            int i = e >> 6, d = e & 63;
            Ks[i * 65 + d] = Kg[(size_t)i * D + d];
            Vs[i * 68 + d] = Vg[(size_t)i * D + d];
        }
        for (int e = tid; e < 127 * 64; e += 256) {
            int lp = e >> 6, d = e & 63;
            Ps[lp * 65 + d] = P[((size_t)(lbase + lp)) * D + h * DK + d];
        }
        if (tid < 64)  ub[tid]  = ubias[(b * H + h) * S + z0 + tid];
        if (tid < 127) bvs[tid] = Bv[h * L + lbase + tid];
        __syncthreads();

        // S[r][j] for j = jj*4 + c4
        float acc[16];
#pragma unroll
        for (int jj = 0; jj < 16; jj++) acc[jj] = 0.f;

#pragma unroll 2
        for (int kk = 0; kk < 64; kk++) {
            float qv = Qs[r * 65 + kk];
#pragma unroll
            for (int jj = 0; jj < 16; jj++) {
                int j = jj * 4 + c4;
                acc[jj] = fmaf(qv, Ks[j * 65 + kk], acc[jj]);
                acc[jj] = fmaf(qv, Ps[(j + prow) * 65 + kk], acc[jj]);
            }
        }

        float tmax = -1e30f;
        float Sv[16];
#pragma unroll
        for (int jj = 0; jj < 16; jj++) {
            int j = jj * 4 + c4;
            float s = (acc[jj] + ub[j] + bvs[j + prow]) * 0.125f;
            if (zt == st && j > r) s = -1e30f;
            Sv[jj] = s;
            tmax = fmaxf(tmax, s);
        }
        tmax = fmaxf(tmax, __shfl_xor_sync(0xffffffffu, tmax, 1));
        tmax = fmaxf(tmax, __shfl_xor_sync(0xffffffffu, tmax, 2));

        float newm  = fmaxf(mrow, tmax);
        float scale = __expf(mrow - newm);

        float psum = 0.f;
#pragma unroll
        for (int jj = 0; jj < 16; jj++) {
            float p = __expf(Sv[jj] - newm);
            Sv[jj] = p;
            psum += p;
        }
        psum += __shfl_xor_sync(0xffffffffu, psum, 1);
        psum += __shfl_xor_sync(0xffffffffu, psum, 2);
        lrow = lrow * scale + psum;
        mrow = newm;

#pragma unroll
        for (int d = 0; d < 16; d++) Ob[d] *= scale;

#pragma unroll
        for (int jj = 0; jj < 16; jj++) Pr[r * 65 + jj * 4 + c4] = Sv[jj];
        __syncthreads();

        // O[r][c4*16 .. +15] += sum_j Pr[r][j] * V[j][..]
#pragma unroll 2
        for (int j = 0; j < 64; j++) {
            float pv = Pr[r * 65 + j];
            const float4* vp = (const float4*)&Vs[j * 68 + c4 * 16];
            float4 v0 = vp[0], v1 = vp[1], v2 = vp[2], v3 = vp[3];
            Ob[0]  = fmaf(pv, v0.x, Ob[0]);  Ob[1]  = fmaf(pv, v0.y, Ob[1]);
            Ob[2]  = fmaf(pv, v0.z, Ob[2]);  Ob[3]  = fmaf(pv, v0.w, Ob[3]);
            Ob[4]  = fmaf(pv, v1.x, Ob[4]);  Ob[5]  = fmaf(pv, v1.y, Ob[5]);
            Ob[6]  = fmaf(pv, v1.z, Ob[6]);  Ob[7]  = fmaf(pv, v1.w, Ob[7]);
            Ob[8]  = fmaf(pv, v2.x, Ob[8]);  Ob[9]  = fmaf(pv, v2.y, Ob[9]);
            Ob[10] = fmaf(pv, v2.z, Ob[10]); Ob[11] = fmaf(pv, v2.w, Ob[11]);
            Ob[12] = fmaf(pv, v3.x, Ob[12]); Ob[13] = fmaf(pv, v3.y, Ob[13]);
            Ob[14] = fmaf(pv, v3.z, Ob[14]); Ob[15] = fmaf(pv, v3.w, Ob[15]);
        }
    }

    float inv = 1.0f / lrow;
    float* Og = O + ((size_t)(b * S + s0 + r)) * D + h * DK + c4 * 16;
#pragma unroll
    for (int d = 0; d < 16; d++) Og[d] = Ob[d] * inv;
}

// ---------------------------------------------------------------------------
// Launch
// ---------------------------------------------------------------------------
extern "C" void kernel_launch(void* const* d_in, const int* in_sizes, int n_in,
                              void* d_out, int out_size)
{
    const float* x      = (const float*)d_in[0];
    const float* Wq     = (const float*)d_in[1];
    const float* bq     = (const float*)d_in[2];
    const float* Wk     = (const float*)d_in[3];
    const float* bk     = (const float*)d_in[4];
    const float* Wv     = (const float*)d_in[5];
    const float* bv     = (const float*)d_in[6];
    const float* Wr     = (const float*)d_in[7];
    const float* br     = (const float*)d_in[8];
    const float* rel_u  = (const float*)d_in[9];
    const float* rel_v  = (const float*)d_in[10];
    const float* Wo     = (const float*)d_in[11];
    const float* bo     = (const float*)d_in[12];
    const float* relpos = (const float*)d_in[13];
    float* out = (float*)d_out;

    float *Qb, *Kb, *Vb, *KRb, *Pb, *PRb, *ubb, *bvb, *vwb;
    cudaGetSymbolAddress((void**)&Qb,  g_Q);
    cudaGetSymbolAddress((void**)&Kb,  g_K);
    cudaGetSymbolAddress((void**)&Vb,  g_V);
    cudaGetSymbolAddress((void**)&KRb, g_KR);
    cudaGetSymbolAddress((void**)&Pb,  g_P);
    cudaGetSymbolAddress((void**)&PRb, g_PR);
    cudaGetSymbolAddress((void**)&ubb, g_ub);
    cudaGetSymbolAddress((void**)&bvb, g_Bv);
    cudaGetSymbolAddress((void**)&vwb, g_VW);

    // R = relpos_table[MAXLEN - s + 1 : MAXLEN + s]  ->  rows [1, 2048), L=2047
    const float* R = relpos + (size_t)1 * D;

    dim3 gfull(D / 128, BS / 128);            // (8, 32)
    dim3 grel(D / 128, (L + 127) / 128);      // (8, 16)

    gemm_bias<<<gfull, 256>>>(x, Wq, bq, Qb,  BS, D, D);
    gemm_bias<<<gfull, 256>>>(x, Wk, bk, Kb,  BS, D, D);
    gemm_bias<<<gfull, 256>>>(x, Wv, bv, Vb,  BS, D, D);
    gemm_bias<<<gfull, 256>>>(x, Wr, br, KRb, BS, D, D);
    gemm_bias<<<grel, 256>>>(R, Wk, bk, Pb,  L, D, D);
    gemm_bias<<<grel, 256>>>(R, Wr, br, PRb, L, D, D);

    ubias_kernel<<<(B * H * S + 255) / 256, 256>>>(KRb, rel_u, ubb);
    bv_kernel<<<(H * L + 255) / 256, 256>>>(PRb, rel_v, bvb);

    const int attn_smem = ATTN_SMEM_FLOATS * (int)sizeof(float);
    cudaFuncSetAttribute(attn_kernel, cudaFuncAttributeMaxDynamicSharedMemorySize,
                         attn_smem);
    attn_kernel<<<dim3(S / 64, B * H), 256, attn_smem>>>(Qb, Kb, Vb, Pb, ubb, bvb, vwb);

    gemm_bias<<<gfull, 256>>>(vwb, Wo, bo, out, BS, D, D);
}

// round 5
// speedup vs baseline: 1.4755x; 1.4755x over previous
#include <cuda_runtime.h>
#include <cuda_bf16.h>
#include <cstdint>

// Problem constants
#define B 4
#define S 1024
#define D 1024
#define H 16
#define DK 64
#define L 2047          // 2*S - 1
#define BS (B*S)        // 4096

// ---------------------------------------------------------------------------
// Scratch (static device globals; no runtime allocation allowed)
// ---------------------------------------------------------------------------
__device__ float g_Q [BS * D];
__device__ float g_K [BS * D];
__device__ float g_V [BS * D];
__device__ float g_KR[BS * D];
__device__ float g_P [L * D];
__device__ float g_PR[L * D];
__device__ float g_ub[B * H * S];
__device__ float g_Bv[H * L];
__device__ float g_VW[BS * D];

// bf16 hi/lo splits
__device__ __nv_bfloat16 g_xh[BS * D], g_xl[BS * D];
__device__ __nv_bfloat16 g_Rh[L * D],  g_Rl[L * D];
__device__ __nv_bfloat16 g_Wsh[5 * D * D], g_Wsl[5 * D * D];   // q,k,v,r,o
__device__ __nv_bfloat16 g_vh[BS * D], g_vl[BS * D];

// ---------------------------------------------------------------------------
// PTX helpers: portable sm_80+ (ldmatrix / mma.sync / cp.async). No 'a'-gated
// features — the harness compiles PTX at target compute_103 (no suffix).
// ---------------------------------------------------------------------------
__device__ __forceinline__ uint32_t smem_to_u32(const void* p) {
    uint32_t a;
    asm("{ .reg .u64 t; cvta.to.shared.u64 t, %1; cvt.u32.u64 %0, t; }"
        : "=r"(a) : "l"(p));
    return a;
}

__device__ __forceinline__ void ldsm4(uint32_t* r, uint32_t addr) {
    asm volatile("ldmatrix.sync.aligned.m8n8.x4.shared.b16 {%0,%1,%2,%3}, [%4];"
                 : "=r"(r[0]), "=r"(r[1]), "=r"(r[2]), "=r"(r[3]) : "r"(addr));
}

__device__ __forceinline__ void mma16816(float* d, const uint32_t* a,
                                         const uint32_t* b) {
    asm volatile(
        "mma.sync.aligned.m16n8k16.row.col.f32.bf16.bf16.f32 "
        "{%0,%1,%2,%3}, {%4,%5,%6,%7}, {%8,%9}, {%0,%1,%2,%3};"
        : "+f"(d[0]), "+f"(d[1]), "+f"(d[2]), "+f"(d[3])
        : "r"(a[0]), "r"(a[1]), "r"(a[2]), "r"(a[3]), "r"(b[0]), "r"(b[1]));
}

__device__ __forceinline__ void cp16(uint32_t dst, const void* src, int sz) {
    asm volatile("cp.async.cg.shared.global [%0], [%1], 16, %2;\n"
                 :: "r"(dst), "l"(src), "r"(sz));
}
__device__ __forceinline__ void cp_commit() {
    asm volatile("cp.async.commit_group;\n" ::: "memory");
}
template <int N> __device__ __forceinline__ void cp_wait() {
    asm volatile("cp.async.wait_group %0;\n" :: "n"(N) : "memory");
}

// ---------------------------------------------------------------------------
// fp32 -> bf16 hi/lo split
// ---------------------------------------------------------------------------
__global__ void split_kernel(const float* __restrict__ s,
                             __nv_bfloat16* __restrict__ hi,
                             __nv_bfloat16* __restrict__ lo, int n)
{
    int i = blockIdx.x * 256 + threadIdx.x;
    if (i < n) {
        float x = s[i];
        __nv_bfloat16 h = __float2bfloat16(x);
        float r = x - __bfloat162float(h);
        hi[i] = h;
        lo[i] = __float2bfloat16(r);
    }
}

// ---------------------------------------------------------------------------
// HMMA GEMM: C[M,1024] = A[M,1024] @ W[1024,1024]^T + bias
// A,W given as bf16 hi/lo pairs; bf16x3 compensation (AhWh + AhWl + AlWh).
// 128x128 CTA tile, 8 warps (2x4 -> 64x32 warp tiles), K-chunk 32,
// cp.async double-buffered. Smem rows padded to 80B (conflict-free ldmatrix).
// ---------------------------------------------------------------------------
struct GemmBatch {
    const __nv_bfloat16* Wh[4];
    const __nv_bfloat16* Wl[4];
    const float* bias[4];
    float* C[4];
};

#define RS      40                   // bf16 elems per smem row (80 bytes)
#define TILE_B  (128 * RS * 2)       // 10240 B: one 128x32 bf16 tile
#define STAGE_B (4 * TILE_B)         // Ah, Al, Wh, Wl
#define GEMM_SMEM (2 * STAGE_B)      // 81920
#define NC      32                   // 1024 / 32 K-chunks

__device__ __forceinline__ void load_chunk(
    uint32_t sbase, int tid,
    const __nv_bfloat16* Ah, const __nv_bfloat16* Al,
    const __nv_bfloat16* Wh, const __nv_bfloat16* Wl,
    int bm, int bn, int M, int c, int st)
{
    const int kbase = c * 32;
    const uint32_t stoff = sbase + st * STAGE_B;
#pragma unroll
    for (int t = 0; t < 4; t++) {
        const __nv_bfloat16* base = (t == 0) ? Ah : (t == 1) ? Al : (t == 2) ? Wh : Wl;
        const int rb = (t < 2) ? bm : bn;
#pragma unroll
        for (int j = 0; j < 2; j++) {
            int idx = tid + j * 256;          // 0..511
            int row = idx >> 2, g = idx & 3;
            int gr = rb + row;
            int sz = (t >= 2 || gr < M) ? 16 : 0;
            const void* src = base + (size_t)gr * 1024 + kbase + g * 8;
            uint32_t dst = stoff + t * TILE_B + row * 80 + g * 16;
            cp16(dst, src, sz);
        }
    }
}

__global__ __launch_bounds__(256, 1)
void gemm_tc(const __nv_bfloat16* __restrict__ Ah,
             const __nv_bfloat16* __restrict__ Al,
             const GemmBatch bat, int M)
{
    extern __shared__ char smem[];
    const uint32_t sbase = smem_to_u32(smem);
    const int tid  = threadIdx.x;
    const int wid  = tid >> 5;
    const int lane = tid & 31;
    const int bn = blockIdx.x * 128;
    const int bm = blockIdx.y * 128;
    const int z  = blockIdx.z;
    const __nv_bfloat16* Wh = bat.Wh[z];
    const __nv_bfloat16* Wl = bat.Wl[z];

    const int mb = (wid >> 2) * 64;   // warp m offset in tile
    const int nb = (wid & 3) * 32;    // warp n offset in tile

    // ldmatrix per-lane address offsets (within a fragment base)
    const int li = lane >> 3, lr = lane & 7;
    const int a_off = ((li & 1) * 8 + lr) * 80 + (li >> 1) * 16;  // A: x4 m16k16
    const int b_off = ((li >> 1) * 8 + lr) * 80 + (li & 1) * 16;  // B: x4 n16k16

    float acc[4][4][4];
#pragma unroll
    for (int mf = 0; mf < 4; mf++)
#pragma unroll
        for (int nf = 0; nf < 4; nf++)
#pragma unroll
            for (int e = 0; e < 4; e++) acc[mf][nf][e] = 0.f;

    // prologue
    load_chunk(sbase, tid, Ah, Al, Wh, Wl, bm, bn, M, 0, 0);
    cp_commit();

    for (int c = 0; c < NC; c++) {
        const int st = c & 1;
        if (c + 1 < NC) {
            load_chunk(sbase, tid, Ah, Al, Wh, Wl, bm, bn, M, c + 1, (c + 1) & 1);
            cp_commit();
            cp_wait<1>();
        } else {
            cp_wait<0>();
        }
        __syncthreads();

        const uint32_t aH = sbase + st * STAGE_B + 0 * TILE_B + (mb)*80 + a_off;
        const uint32_t aL = aH + TILE_B;
        const uint32_t wH = sbase + st * STAGE_B + 2 * TILE_B + (nb)*80 + b_off;
        const uint32_t wL = wH + TILE_B;

#pragma unroll
        for (int k16 = 0; k16 < 2; k16++) {
            const int ko = k16 * 32;     // byte offset of k0 within row
            uint32_t ah[4][4], al[4][4], bh[2][4], bl[2][4];
#pragma unroll
            for (int mf = 0; mf < 4; mf++) {
                ldsm4(ah[mf], aH + mf * 16 * 80 + ko);
                ldsm4(al[mf], aL + mf * 16 * 80 + ko);
            }
#pragma unroll
            for (int n2 = 0; n2 < 2; n2++) {
                ldsm4(bh[n2], wH + n2 * 16 * 80 + ko);
                ldsm4(bl[n2], wL + n2 * 16 * 80 + ko);
            }
#pragma unroll
            for (int mf = 0; mf < 4; mf++)
#pragma unroll
                for (int nf = 0; nf < 4; nf++) {
                    const uint32_t* bph = &bh[nf >> 1][(nf & 1) * 2];
                    const uint32_t* bpl = &bl[nf >> 1][(nf & 1) * 2];
                    mma16816(acc[mf][nf], ah[mf], bph);
                    mma16816(acc[mf][nf], ah[mf], bpl);
                    mma16816(acc[mf][nf], al[mf], bph);
                }
        }
        __syncthreads();
    }

    // epilogue: direct STG with bias
    const float* bias = bat.bias[z];
    float* C = bat.C[z];
    const int lr4 = lane >> 2, lc2 = (lane & 3) * 2;
#pragma unroll
    for (int mf = 0; mf < 4; mf++) {
#pragma unroll
        for (int nf = 0; nf < 4; nf++) {
            int gn = bn + nb + nf * 8 + lc2;
            float2 bi = *(const float2*)(bias + gn);
            int gm0 = bm + mb + mf * 16 + lr4;
            if (gm0 < M) {
                float2 v = make_float2(acc[mf][nf][0] + bi.x, acc[mf][nf][1] + bi.y);
                *(float2*)(C + (size_t)gm0 * 1024 + gn) = v;
            }
            int gm1 = gm0 + 8;
            if (gm1 < M) {
                float2 v = make_float2(acc[mf][nf][2] + bi.x, acc[mf][nf][3] + bi.y);
                *(float2*)(C + (size_t)gm1 * 1024 + gn) = v;
            }
        }
    }
}

// ---------------------------------------------------------------------------
// ubias[b,h,z] = sum_d rel_u[h,d] * KR[b,z,h,d]
// ---------------------------------------------------------------------------
__global__ void ubias_kernel(const float* __restrict__ KR,
                             const float* __restrict__ rel_u,
                             float* __restrict__ ub)
{
    int idx = blockIdx.x * 256 + threadIdx.x;
    if (idx >= B * H * S) return;
    int z = idx & (S - 1);
    int h = (idx >> 10) & (H - 1);
    int b = idx >> 14;
    const float* kr = KR + ((size_t)(b * S + z)) * D + h * DK;
    const float* ru = rel_u + h * DK;
    float s = 0.f;
#pragma unroll
    for (int d = 0; d < DK; d++) s = fmaf(kr[d], ru[d], s);
    ub[idx] = s;
}

__global__ void bv_kernel(const float* __restrict__ PR,
                          const float* __restrict__ rel_v,
                          float* __restrict__ Bv)
{
    int idx = blockIdx.x * 256 + threadIdx.x;
    if (idx >= H * L) return;
    int l = idx % L;
    int h = idx / L;
    const float* pr = PR + (size_t)l * D + h * DK;
    const float* rv = rel_v + h * DK;
    float s = 0.f;
#pragma unroll
    for (int d = 0; d < DK; d++) s = fmaf(pr[d], rv[d], s);
    Bv[h * L + l] = s;
}

// ---------------------------------------------------------------------------
// Fused relative attention (flash-style, causal) — proven R1 version
// ---------------------------------------------------------------------------
#define ATTN_SMEM_FLOATS (64*65 + 64*65 + 64*68 + 127*65 + 64*65 + 64 + 128)

__global__ __launch_bounds__(256) void attn_kernel(
    const float* __restrict__ Q, const float* __restrict__ K,
    const float* __restrict__ V, const float* __restrict__ P,
    const float* __restrict__ ubias, const float* __restrict__ Bv,
    float* __restrict__ O)
{
    const int st = blockIdx.x;
    const int b  = blockIdx.y >> 4;
    const int h  = blockIdx.y & 15;
    const int tid = threadIdx.x;
    const int r  = tid >> 2;
    const int c4 = tid & 3;
    const int s0 = st * 64;

    extern __shared__ float sm[];
    float* Qs  = sm;
    float* Ks  = Qs + 64 * 65;
    float* Vs  = Ks + 64 * 65;
    float* Ps  = Vs + 64 * 68;
    float* Pr  = Ps + 127 * 65;
    float* ub  = Pr + 64 * 65;
    float* bvs = ub + 64;

    const float* Qg = Q + ((size_t)(b * S + s0)) * D + h * DK;
    for (int e = tid; e < 64 * 64; e += 256) {
        int i = e >> 6, d = e & 63;
        Qs[i * 65 + d] = Qg[(size_t)i * D + d];
    }

    float Ob[16];
#pragma unroll
    for (int d = 0; d < 16; d++) Ob[d] = 0.f;
    float mrow = -1e30f, lrow = 0.f;

    const int prow = 63 - r;

    for (int zt = 0; zt <= st; zt++) {
        const int z0 = zt * 64;
        const int lbase = (zt - st) * 64 + 960;

        __syncthreads();

        const float* Kg = K + ((size_t)(b * S + z0)) * D + h * DK;
        const float* Vg = V + ((size_t)(b * S + z0)) * D + h * DK;
        for (int e = tid; e < 64 * 64; e += 256) {
            int i = e >> 6, d = e & 63;
            Ks[i * 65 + d] = Kg[(size_t)i * D + d];
            Vs[i * 68 + d] = Vg[(size_t)i * D + d];
        }
        for (int e = tid; e < 127 * 64; e += 256) {
            int lp = e >> 6, d = e & 63;
            Ps[lp * 65 + d] = P[((size_t)(lbase + lp)) * D + h * DK + d];
        }
        if (tid < 64)  ub[tid]  = ubias[(b * H + h) * S + z0 + tid];
        if (tid < 127) bvs[tid] = Bv[h * L + lbase + tid];
        __syncthreads();

        float acc[16];
#pragma unroll
        for (int jj = 0; jj < 16; jj++) acc[jj] = 0.f;

#pragma unroll 2
        for (int kk = 0; kk < 64; kk++) {
            float qv = Qs[r * 65 + kk];
#pragma unroll
            for (int jj = 0; jj < 16; jj++) {
                int j = jj * 4 + c4;
                acc[jj] = fmaf(qv, Ks[j * 65 + kk], acc[jj]);
                acc[jj] = fmaf(qv, Ps[(j + prow) * 65 + kk], acc[jj]);
            }
        }

        float tmax = -1e30f;
        float Sv[16];
#pragma unroll
        for (int jj = 0; jj < 16; jj++) {
            int j = jj * 4 + c4;
            float s = (acc[jj] + ub[j] + bvs[j + prow]) * 0.125f;
            if (zt == st && j > r) s = -1e30f;
            Sv[jj] = s;
            tmax = fmaxf(tmax, s);
        }
        tmax = fmaxf(tmax, __shfl_xor_sync(0xffffffffu, tmax, 1));
        tmax = fmaxf(tmax, __shfl_xor_sync(0xffffffffu, tmax, 2));

        float newm  = fmaxf(mrow, tmax);
        float scale = __expf(mrow - newm);

        float psum = 0.f;
#pragma unroll
        for (int jj = 0; jj < 16; jj++) {
            float p = __expf(Sv[jj] - newm);
            Sv[jj] = p;
            psum += p;
        }
        psum += __shfl_xor_sync(0xffffffffu, psum, 1);
        psum += __shfl_xor_sync(0xffffffffu, psum, 2);
        lrow = lrow * scale + psum;
        mrow = newm;

#pragma unroll
        for (int d = 0; d < 16; d++) Ob[d] *= scale;

#pragma unroll
        for (int jj = 0; jj < 16; jj++) Pr[r * 65 + jj * 4 + c4] = Sv[jj];
        __syncthreads();

#pragma unroll 2
        for (int j = 0; j < 64; j++) {
            float pv = Pr[r * 65 + j];
            const float4* vp = (const float4*)&Vs[j * 68 + c4 * 16];
            float4 v0 = vp[0], v1 = vp[1], v2 = vp[2], v3 = vp[3];
            Ob[0]  = fmaf(pv, v0.x, Ob[0]);  Ob[1]  = fmaf(pv, v0.y, Ob[1]);
            Ob[2]  = fmaf(pv, v0.z, Ob[2]);  Ob[3]  = fmaf(pv, v0.w, Ob[3]);
            Ob[4]  = fmaf(pv, v1.x, Ob[4]);  Ob[5]  = fmaf(pv, v1.y, Ob[5]);
            Ob[6]  = fmaf(pv, v1.z, Ob[6]);  Ob[7]  = fmaf(pv, v1.w, Ob[7]);
            Ob[8]  = fmaf(pv, v2.x, Ob[8]);  Ob[9]  = fmaf(pv, v2.y, Ob[9]);
            Ob[10] = fmaf(pv, v2.z, Ob[10]); Ob[11] = fmaf(pv, v2.w, Ob[11]);
            Ob[12] = fmaf(pv, v3.x, Ob[12]); Ob[13] = fmaf(pv, v3.y, Ob[13]);
            Ob[14] = fmaf(pv, v3.z, Ob[14]); Ob[15] = fmaf(pv, v3.w, Ob[15]);
        }
    }

    float inv = 1.0f / lrow;
    float* Og = O + ((size_t)(b * S + s0 + r)) * D + h * DK + c4 * 16;
#pragma unroll
    for (int d = 0; d < 16; d++) Og[d] = Ob[d] * inv;
}

// ---------------------------------------------------------------------------
// Launch
// ---------------------------------------------------------------------------
extern "C" void kernel_launch(void* const* d_in, const int* in_sizes, int n_in,
                              void* d_out, int out_size)
{
    const float* x      = (const float*)d_in[0];
    const float* Wq     = (const float*)d_in[1];
    const float* bq     = (const float*)d_in[2];
    const float* Wk     = (const float*)d_in[3];
    const float* bk     = (const float*)d_in[4];
    const float* Wv     = (const float*)d_in[5];
    const float* bv     = (const float*)d_in[6];
    const float* Wr     = (const float*)d_in[7];
    const float* br     = (const float*)d_in[8];
    const float* rel_u  = (const float*)d_in[9];
    const float* rel_v  = (const float*)d_in[10];
    const float* Wo     = (const float*)d_in[11];
    const float* bo     = (const float*)d_in[12];
    const float* relpos = (const float*)d_in[13];
    float* out = (float*)d_out;

    float *Qb, *Kb, *Vb, *KRb, *Pb, *PRb, *ubb, *bvb, *vwb;
    cudaGetSymbolAddress((void**)&Qb,  g_Q);
    cudaGetSymbolAddress((void**)&Kb,  g_K);
    cudaGetSymbolAddress((void**)&Vb,  g_V);
    cudaGetSymbolAddress((void**)&KRb, g_KR);
    cudaGetSymbolAddress((void**)&Pb,  g_P);
    cudaGetSymbolAddress((void**)&PRb, g_PR);
    cudaGetSymbolAddress((void**)&ubb, g_ub);
    cudaGetSymbolAddress((void**)&bvb, g_Bv);
    cudaGetSymbolAddress((void**)&vwb, g_VW);

    __nv_bfloat16 *xh, *xl, *Rh, *Rl, *Wsh, *Wsl, *vh, *vl;
    cudaGetSymbolAddress((void**)&xh,  g_xh);
    cudaGetSymbolAddress((void**)&xl,  g_xl);
    cudaGetSymbolAddress((void**)&Rh,  g_Rh);
    cudaGetSymbolAddress((void**)&Rl,  g_Rl);
    cudaGetSymbolAddress((void**)&Wsh, g_Wsh);
    cudaGetSymbolAddress((void**)&Wsl, g_Wsl);
    cudaGetSymbolAddress((void**)&vh,  g_vh);
    cudaGetSymbolAddress((void**)&vl,  g_vl);

    const float* R = relpos + (size_t)1 * D;   // rows [1, 2048), L = 2047

    // --- splits ---
    split_kernel<<<(BS * D + 255) / 256, 256>>>(x, xh, xl, BS * D);
    const float* Ws[5] = {Wq, Wk, Wv, Wr, Wo};
    for (int i = 0; i < 5; i++)
        split_kernel<<<(D * D + 255) / 256, 256>>>(Ws[i], Wsh + (size_t)i * D * D,
                                                   Wsl + (size_t)i * D * D, D * D);
    split_kernel<<<(L * D + 255) / 256, 256>>>(R, Rh, Rl, L * D);

    cudaFuncSetAttribute(gemm_tc, cudaFuncAttributeMaxDynamicSharedMemorySize,
                         GEMM_SMEM);

    // --- Q/K/V/KR projections (batched, grid.z = 4) ---
    GemmBatch b1;
    b1.Wh[0] = Wsh + 0 * (size_t)D * D; b1.Wl[0] = Wsl + 0 * (size_t)D * D; b1.bias[0] = bq; b1.C[0] = Qb;
    b1.Wh[1] = Wsh + 1 * (size_t)D * D; b1.Wl[1] = Wsl + 1 * (size_t)D * D; b1.bias[1] = bk; b1.C[1] = Kb;
    b1.Wh[2] = Wsh + 2 * (size_t)D * D; b1.Wl[2] = Wsl + 2 * (size_t)D * D; b1.bias[2] = bv; b1.C[2] = Vb;
    b1.Wh[3] = Wsh + 3 * (size_t)D * D; b1.Wl[3] = Wsl + 3 * (size_t)D * D; b1.bias[3] = br; b1.C[3] = KRb;
    gemm_tc<<<dim3(8, 32, 4), 256, GEMM_SMEM>>>(xh, xl, b1, BS);

    // --- P/PR projections (batched, grid.z = 2) ---
    GemmBatch b2;
    b2.Wh[0] = Wsh + 1 * (size_t)D * D; b2.Wl[0] = Wsl + 1 * (size_t)D * D; b2.bias[0] = bk; b2.C[0] = Pb;
    b2.Wh[1] = Wsh + 3 * (size_t)D * D; b2.Wl[1] = Wsl + 3 * (size_t)D * D; b2.bias[1] = br; b2.C[1] = PRb;
    b2.Wh[2] = b2.Wh[0]; b2.Wl[2] = b2.Wl[0]; b2.bias[2] = bk; b2.C[2] = Pb;
    b2.Wh[3] = b2.Wh[0]; b2.Wl[3] = b2.Wl[0]; b2.bias[3] = bk; b2.C[3] = Pb;
    gemm_tc<<<dim3(8, 16, 2), 256, GEMM_SMEM>>>(Rh, Rl, b2, L);

    ubias_kernel<<<(B * H * S + 255) / 256, 256>>>(KRb, rel_u, ubb);
    bv_kernel<<<(H * L + 255) / 256, 256>>>(PRb, rel_v, bvb);

    const int attn_smem = ATTN_SMEM_FLOATS * (int)sizeof(float);
    cudaFuncSetAttribute(attn_kernel, cudaFuncAttributeMaxDynamicSharedMemorySize,
                         attn_smem);
    attn_kernel<<<dim3(S / 64, B * H), 256, attn_smem>>>(Qb, Kb, Vb, Pb, ubb, bvb, vwb);

    // --- output projection ---
    split_kernel<<<(BS * D + 255) / 256, 256>>>(vwb, vh, vl, BS * D);
    GemmBatch b3;
    b3.Wh[0] = Wsh + 4 * (size_t)D * D; b3.Wl[0] = Wsl + 4 * (size_t)D * D; b3.bias[0] = bo; b3.C[0] = out;
    b3.Wh[1] = b3.Wh[0]; b3.Wl[1] = b3.Wl[0]; b3.bias[1] = bo; b3.C[1] = out;
    b3.Wh[2] = b3.Wh[0]; b3.Wl[2] = b3.Wl[0]; b3.bias[2] = bo; b3.C[2] = out;
    b3.Wh[3] = b3.Wh[0]; b3.Wl[3] = b3.Wl[0]; b3.bias[3] = bo; b3.C[3] = out;
    gemm_tc<<<dim3(8, 32, 1), 256, GEMM_SMEM>>>(vh, vl, b3, BS);
}

// round 7
// speedup vs baseline: 3.6183x; 2.4522x over previous
#include <cuda_runtime.h>
#include <cuda_bf16.h>
#include <cstdint>

// Problem constants
#define B 4
#define S 1024
#define D 1024
#define H 16
#define DK 64
#define L 2047          // 2*S - 1
#define BS (B*S)        // 4096

// ---------------------------------------------------------------------------
// Scratch (static device globals; no runtime allocation allowed)
// ---------------------------------------------------------------------------
__device__ float g_KR[BS * D];
__device__ float g_PR[L * D];
__device__ float g_ub[B * H * S];
__device__ float g_Bv[H * L];

// bf16 hi/lo splits (inputs to tensor-core GEMMs)
__device__ __nv_bfloat16 g_xh[BS * D], g_xl[BS * D];
__device__ __nv_bfloat16 g_Rh[L * D],  g_Rl[L * D];
__device__ __nv_bfloat16 g_Wsh[5 * D * D], g_Wsl[5 * D * D];   // q,k,v,r,o

// bf16 hi/lo GEMM outputs (attention inputs)
__device__ __nv_bfloat16 g_Qbh[BS * D], g_Qbl[BS * D];
__device__ __nv_bfloat16 g_Kbh[BS * D], g_Kbl[BS * D];
__device__ __nv_bfloat16 g_Vbh[BS * D], g_Vbl[BS * D];
__device__ __nv_bfloat16 g_Pbh[L * D],  g_Pbl[L * D];

// attention output (bf16 pairs; input to out-projection)
__device__ __nv_bfloat16 g_vh[BS * D], g_vl[BS * D];

// ---------------------------------------------------------------------------
// PTX helpers: portable sm_80+ (ldmatrix / mma.sync / cp.async).
// ---------------------------------------------------------------------------
__device__ __forceinline__ uint32_t smem_to_u32(const void* p) {
    uint32_t a;
    asm("{ .reg .u64 t; cvta.to.shared.u64 t, %1; cvt.u32.u64 %0, t; }"
        : "=r"(a) : "l"(p));
    return a;
}

__device__ __forceinline__ void ldsm4(uint32_t* r, uint32_t addr) {
    asm volatile("ldmatrix.sync.aligned.m8n8.x4.shared.b16 {%0,%1,%2,%3}, [%4];"
                 : "=r"(r[0]), "=r"(r[1]), "=r"(r[2]), "=r"(r[3]) : "r"(addr));
}
__device__ __forceinline__ void ldsm4t(uint32_t* r, uint32_t addr) {
    asm volatile("ldmatrix.sync.aligned.m8n8.x4.trans.shared.b16 {%0,%1,%2,%3}, [%4];"
                 : "=r"(r[0]), "=r"(r[1]), "=r"(r[2]), "=r"(r[3]) : "r"(addr));
}

__device__ __forceinline__ void mma16816(float* d, const uint32_t* a,
                                         const uint32_t* b) {
    asm volatile(
        "mma.sync.aligned.m16n8k16.row.col.f32.bf16.bf16.f32 "
        "{%0,%1,%2,%3}, {%4,%5,%6,%7}, {%8,%9}, {%0,%1,%2,%3};"
        : "+f"(d[0]), "+f"(d[1]), "+f"(d[2]), "+f"(d[3])
        : "r"(a[0]), "r"(a[1]), "r"(a[2]), "r"(a[3]), "r"(b[0]), "r"(b[1]));
}

__device__ __forceinline__ void cp16(uint32_t dst, const void* src, int sz) {
    asm volatile("cp.async.cg.shared.global [%0], [%1], 16, %2;\n"
                 :: "r"(dst), "l"(src), "r"(sz));
}
__device__ __forceinline__ void cp_commit() {
    asm volatile("cp.async.commit_group;\n" ::: "memory");
}
template <int N> __device__ __forceinline__ void cp_wait() {
    asm volatile("cp.async.wait_group %0;\n" :: "n"(N) : "memory");
}

// ---------------------------------------------------------------------------
// fp32 -> bf16 hi/lo split
// ---------------------------------------------------------------------------
__global__ void split_kernel(const float* __restrict__ s,
                             __nv_bfloat16* __restrict__ hi,
                             __nv_bfloat16* __restrict__ lo, int n)
{
    int i = blockIdx.x * 256 + threadIdx.x;
    if (i < n) {
        float x = s[i];
        __nv_bfloat16 h = __float2bfloat16(x);
        float r = x - __bfloat162float(h);
        hi[i] = h;
        lo[i] = __float2bfloat16(r);
    }
}

// ---------------------------------------------------------------------------
// HMMA GEMM: C[M,1024] = A[M,1024] @ W[1024,1024]^T + bias
// bf16x3 compensation. mode 0: fp32 C;  mode 1: bf16 hi/lo pair outputs.
// ---------------------------------------------------------------------------
struct GemmBatch {
    const __nv_bfloat16* Wh[4];
    const __nv_bfloat16* Wl[4];
    const float* bias[4];
    float* C[4];
    __nv_bfloat16* Ch[4];
    __nv_bfloat16* Cl[4];
    int mode[4];
};

#define RS      40                   // bf16 elems per smem row (80 bytes)
#define TILE_B  (128 * RS * 2)       // 10240 B
#define STAGE_B (4 * TILE_B)
#define GEMM_SMEM (2 * STAGE_B)      // 81920
#define NC      32

__device__ __forceinline__ void load_chunk(
    uint32_t sbase, int tid,
    const __nv_bfloat16* Ah, const __nv_bfloat16* Al,
    const __nv_bfloat16* Wh, const __nv_bfloat16* Wl,
    int bm, int bn, int M, int c, int st)
{
    const int kbase = c * 32;
    const uint32_t stoff = sbase + st * STAGE_B;
#pragma unroll
    for (int t = 0; t < 4; t++) {
        const __nv_bfloat16* base = (t == 0) ? Ah : (t == 1) ? Al : (t == 2) ? Wh : Wl;
        const int rb = (t < 2) ? bm : bn;
#pragma unroll
        for (int j = 0; j < 2; j++) {
            int idx = tid + j * 256;
            int row = idx >> 2, g = idx & 3;
            int gr = rb + row;
            int sz = (t >= 2 || gr < M) ? 16 : 0;
            const void* src = base + (size_t)gr * 1024 + kbase + g * 8;
            uint32_t dst = stoff + t * TILE_B + row * 80 + g * 16;
            cp16(dst, src, sz);
        }
    }
}

__global__ __launch_bounds__(256, 1)
void gemm_tc(const __nv_bfloat16* __restrict__ Ah,
             const __nv_bfloat16* __restrict__ Al,
             const GemmBatch bat, int M)
{
    extern __shared__ char smem[];
    const uint32_t sbase = smem_to_u32(smem);
    const int tid  = threadIdx.x;
    const int wid  = tid >> 5;
    const int lane = tid & 31;
    const int bn = blockIdx.x * 128;
    const int bm = blockIdx.y * 128;
    const int z  = blockIdx.z;
    const __nv_bfloat16* Wh = bat.Wh[z];
    const __nv_bfloat16* Wl = bat.Wl[z];

    const int mb = (wid >> 2) * 64;
    const int nb = (wid & 3) * 32;

    const int li = lane >> 3, lr = lane & 7;
    const int a_off = ((li & 1) * 8 + lr) * 80 + (li >> 1) * 16;
    const int b_off = ((li >> 1) * 8 + lr) * 80 + (li & 1) * 16;

    float acc[4][4][4];
#pragma unroll
    for (int mf = 0; mf < 4; mf++)
#pragma unroll
        for (int nf = 0; nf < 4; nf++)
#pragma unroll
            for (int e = 0; e < 4; e++) acc[mf][nf][e] = 0.f;

    load_chunk(sbase, tid, Ah, Al, Wh, Wl, bm, bn, M, 0, 0);
    cp_commit();

    for (int c = 0; c < NC; c++) {
        const int st = c & 1;
        if (c + 1 < NC) {
            load_chunk(sbase, tid, Ah, Al, Wh, Wl, bm, bn, M, c + 1, (c + 1) & 1);
            cp_commit();
            cp_wait<1>();
        } else {
            cp_wait<0>();
        }
        __syncthreads();

        const uint32_t aH = sbase + st * STAGE_B + 0 * TILE_B + (mb)*80 + a_off;
        const uint32_t aL = aH + TILE_B;
        const uint32_t wH = sbase + st * STAGE_B + 2 * TILE_B + (nb)*80 + b_off;
        const uint32_t wL = wH + TILE_B;

#pragma unroll
        for (int k16 = 0; k16 < 2; k16++) {
            const int ko = k16 * 32;
            uint32_t ah[4][4], al[4][4], bh[2][4], bl[2][4];
#pragma unroll
            for (int mf = 0; mf < 4; mf++) {
                ldsm4(ah[mf], aH + mf * 16 * 80 + ko);
                ldsm4(al[mf], aL + mf * 16 * 80 + ko);
            }
#pragma unroll
            for (int n2 = 0; n2 < 2; n2++) {
                ldsm4(bh[n2], wH + n2 * 16 * 80 + ko);
                ldsm4(bl[n2], wL + n2 * 16 * 80 + ko);
            }
#pragma unroll
            for (int mf = 0; mf < 4; mf++)
#pragma unroll
                for (int nf = 0; nf < 4; nf++) {
                    const uint32_t* bph = &bh[nf >> 1][(nf & 1) * 2];
                    const uint32_t* bpl = &bl[nf >> 1][(nf & 1) * 2];
                    mma16816(acc[mf][nf], ah[mf], bph);
                    mma16816(acc[mf][nf], ah[mf], bpl);
                    mma16816(acc[mf][nf], al[mf], bph);
                }
        }
        __syncthreads();
    }

    const float* bias = bat.bias[z];
    const int lr4 = lane >> 2, lc2 = (lane & 3) * 2;
    if (bat.mode[z] == 0) {
        float* C = bat.C[z];
#pragma unroll
        for (int mf = 0; mf < 4; mf++)
#pragma unroll
            for (int nf = 0; nf < 4; nf++) {
                int gn = bn + nb + nf * 8 + lc2;
                float2 bi = *(const float2*)(bias + gn);
                int gm0 = bm + mb + mf * 16 + lr4;
                if (gm0 < M) {
                    float2 v = make_float2(acc[mf][nf][0] + bi.x, acc[mf][nf][1] + bi.y);
                    *(float2*)(C + (size_t)gm0 * 1024 + gn) = v;
                }
                int gm1 = gm0 + 8;
                if (gm1 < M) {
                    float2 v = make_float2(acc[mf][nf][2] + bi.x, acc[mf][nf][3] + bi.y);
                    *(float2*)(C + (size_t)gm1 * 1024 + gn) = v;
                }
            }
    } else {
        __nv_bfloat16* Ch = bat.Ch[z];
        __nv_bfloat16* Cl = bat.Cl[z];
#pragma unroll
        for (int mf = 0; mf < 4; mf++)
#pragma unroll
            for (int nf = 0; nf < 4; nf++) {
                int gn = bn + nb + nf * 8 + lc2;
                float2 bi = *(const float2*)(bias + gn);
#pragma unroll
                for (int half = 0; half < 2; half++) {
                    int gm = bm + mb + mf * 16 + lr4 + half * 8;
                    if (gm < M) {
                        float vx = acc[mf][nf][half * 2 + 0] + bi.x;
                        float vy = acc[mf][nf][half * 2 + 1] + bi.y;
                        __nv_bfloat16 hx = __float2bfloat16(vx);
                        __nv_bfloat16 hy = __float2bfloat16(vy);
                        __nv_bfloat162 hv; hv.x = hx; hv.y = hy;
                        __nv_bfloat162 lv;
                        lv.x = __float2bfloat16(vx - __bfloat162float(hx));
                        lv.y = __float2bfloat16(vy - __bfloat162float(hy));
                        *(__nv_bfloat162*)(Ch + (size_t)gm * 1024 + gn) = hv;
                        *(__nv_bfloat162*)(Cl + (size_t)gm * 1024 + gn) = lv;
                    }
                }
            }
    }
}

// ---------------------------------------------------------------------------
// ubias / Bv reductions (fp32 inputs)
// ---------------------------------------------------------------------------
__global__ void ubias_kernel(const float* __restrict__ KR,
                             const float* __restrict__ rel_u,
                             float* __restrict__ ub)
{
    int idx = blockIdx.x * 256 + threadIdx.x;
    if (idx >= B * H * S) return;
    int z = idx & (S - 1);
    int h = (idx >> 10) & (H - 1);
    int b = idx >> 14;
    const float* kr = KR + ((size_t)(b * S + z)) * D + h * DK;
    const float* ru = rel_u + h * DK;
    float s = 0.f;
#pragma unroll
    for (int d = 0; d < DK; d++) s = fmaf(kr[d], ru[d], s);
    ub[idx] = s;
}

__global__ void bv_kernel(const float* __restrict__ PR,
                          const float* __restrict__ rel_v,
                          float* __restrict__ Bv)
{
    int idx = blockIdx.x * 256 + threadIdx.x;
    if (idx >= H * L) return;
    int l = idx % L;
    int h = idx / L;
    const float* pr = PR + (size_t)l * D + h * DK;
    const float* rv = rel_v + h * DK;
    float s = 0.f;
#pragma unroll
    for (int d = 0; d < DK; d++) s = fmaf(pr[d], rv[d], s);
    Bv[h * L + l] = s;
}

// ---------------------------------------------------------------------------
// Tensorized fused relative attention (flash-style, causal, bf16x3 MMA).
// CTA: 64 q-rows, 4 warps (warp w -> rows 16w..16w+15). 64-col KV tiles.
// ---------------------------------------------------------------------------
#define ATS      144                 // smem row stride bytes (72 bf16)
#define ST_KH    0
#define ST_KL    9216
#define ST_VH    18432
#define ST_VL    27648
#define ST_PH    36864               // 128 rows
#define ST_PL    55296
#define ST_UB    73728               // 64 floats
#define ST_BV    73984               // 127 floats (+pad)
#define ST_SIZE  74496
#define SM_Q     0                   // Qh 9216, Ql 9216
#define SM_ST    18432
#define SM_QPS   (18432 + 2 * ST_SIZE)          // 167424: fp32 64 x 132
#define SM_PRB   (SM_QPS + 33792)               // 201216: phs 9216, pls 9216
#define ATTN_SMEM_BYTES (SM_PRB + 18432)        // 219648

__device__ __forceinline__ void attn_load_stage(
    uint32_t stg, int tid,
    const __nv_bfloat16* Kh, const __nv_bfloat16* Kl,
    const __nv_bfloat16* Vh, const __nv_bfloat16* Vl,
    const __nv_bfloat16* Ph, const __nv_bfloat16* Pl)
{
#pragma unroll
    for (int j = 0; j < 4; j++) {
        int idx = tid + j * 128;
        int row = idx >> 3, g = idx & 7;
        const size_t go = (size_t)row * D + g * 8;
        uint32_t so = row * ATS + g * 16;
        cp16(stg + ST_KH + so, Kh + go, 16);
        cp16(stg + ST_KL + so, Kl + go, 16);
        cp16(stg + ST_VH + so, Vh + go, 16);
        cp16(stg + ST_VL + so, Vl + go, 16);
    }
#pragma unroll
    for (int j = 0; j < 8; j++) {
        int idx = tid + j * 128;
        if (idx < 1016) {                       // 127 rows x 8 segs
            int row = idx >> 3, g = idx & 7;
            const size_t go = (size_t)row * D + g * 8;
            uint32_t so = row * ATS + g * 16;
            cp16(stg + ST_PH + so, Ph + go, 16);
            cp16(stg + ST_PL + so, Pl + go, 16);
        }
    }
}

__global__ __launch_bounds__(128, 1) void attn_mma(
    const __nv_bfloat16* __restrict__ Qh, const __nv_bfloat16* __restrict__ Ql,
    const __nv_bfloat16* __restrict__ Kh, const __nv_bfloat16* __restrict__ Kl,
    const __nv_bfloat16* __restrict__ Vh, const __nv_bfloat16* __restrict__ Vl,
    const __nv_bfloat16* __restrict__ Ph, const __nv_bfloat16* __restrict__ Pl,
    const float* __restrict__ ubias, const float* __restrict__ Bv,
    __nv_bfloat16* __restrict__ Oh, __nv_bfloat16* __restrict__ Ol)
{
    extern __shared__ char smem[];
    const uint32_t sb = smem_to_u32(smem);
    const int tid  = threadIdx.x;
    const int wid  = tid >> 5;
    const int lane = tid & 31;
    const int st = blockIdx.x;
    const int b  = blockIdx.y >> 4;
    const int h  = blockIdx.y & 15;
    const int s0 = st * 64;

    const int li = lane >> 3, lr = lane & 7;
    const int a_off = ((li & 1) * 8 + lr) * ATS + (li >> 1) * 16;   // A (and trans-B)
    const int b_off = ((li >> 1) * 8 + lr) * ATS + (li & 1) * 16;   // B col-major

    const int r0 = wid * 16 + (lane >> 2);       // row of c-frag elems 0,1
    const int colbase = (lane & 3) * 2;

    // -------- prologue: Q tile + stage 0 --------
    {
        const __nv_bfloat16* Qgh = Qh + (size_t)(b * S + s0) * D + h * DK;
        const __nv_bfloat16* Qgl = Ql + (size_t)(b * S + s0) * D + h * DK;
#pragma unroll
        for (int j = 0; j < 4; j++) {
            int idx = tid + j * 128;
            int row = idx >> 3, g = idx & 7;
            const size_t go = (size_t)row * D + g * 8;
            uint32_t so = row * ATS + g * 16;
            cp16(sb + SM_Q + so, Qgh + go, 16);
            cp16(sb + SM_Q + 9216 + so, Qgl + go, 16);
        }
        const size_t kvoff = (size_t)(b * S) * D + h * DK;   // + z0*D later
        int lbase0 = -st * 64 + 960;
        attn_load_stage(sb + SM_ST, tid,
                        Kh + kvoff, Kl + kvoff, Vh + kvoff, Vl + kvoff,
                        Ph + (size_t)lbase0 * D + h * DK,
                        Pl + (size_t)lbase0 * D + h * DK);
        float* ubS = (float*)(smem + SM_ST + ST_UB);
        float* bvS = (float*)(smem + SM_ST + ST_BV);
        if (tid < 64)  ubS[tid] = ubias[(b * H + h) * S + tid];
        if (tid < 127) bvS[tid] = Bv[h * L + lbase0 + tid];
        cp_commit();
    }

    float cO[8][4];
#pragma unroll
    for (int nf = 0; nf < 8; nf++)
#pragma unroll
        for (int e = 0; e < 4; e++) cO[nf][e] = 0.f;
    float mrow[2] = {-1e30f, -1e30f};
    float lsum[2] = {0.f, 0.f};

    for (int zt = 0; zt <= st; zt++) {
        const int s = zt & 1;
        const uint32_t stg = sb + SM_ST + s * ST_SIZE;

        cp_wait<0>();
        __syncthreads();

        if (zt < st) {
            const int z1 = (zt + 1) * 64;
            const int lb1 = (zt + 1 - st) * 64 + 960;
            const size_t kvoff = (size_t)(b * S + z1) * D + h * DK;
            uint32_t nstg = sb + SM_ST + (s ^ 1) * ST_SIZE;
            attn_load_stage(nstg, tid,
                            Kh + kvoff, Kl + kvoff, Vh + kvoff, Vl + kvoff,
                            Ph + (size_t)lb1 * D + h * DK,
                            Pl + (size_t)lb1 * D + h * DK);
            float* ubS = (float*)(smem + SM_ST + (s ^ 1) * ST_SIZE + ST_UB);
            float* bvS = (float*)(smem + SM_ST + (s ^ 1) * ST_SIZE + ST_BV);
            if (tid < 64)  ubS[tid] = ubias[(b * H + h) * S + z1 + tid];
            if (tid < 127) bvS[tid] = Bv[h * L + lb1 + tid];
            cp_commit();
        }

        // -------- QP (64x128) and QK (64x64) MMA, bf16x3 --------
        float cQP[16][4], cQK[8][4];
#pragma unroll
        for (int nf = 0; nf < 16; nf++)
#pragma unroll
            for (int e = 0; e < 4; e++) cQP[nf][e] = 0.f;
#pragma unroll
        for (int nf = 0; nf < 8; nf++)
#pragma unroll
            for (int e = 0; e < 4; e++) cQK[nf][e] = 0.f;

#pragma unroll
        for (int k16 = 0; k16 < 4; k16++) {
            const int ko = k16 * 32;
            uint32_t qh[4], ql[4];
            ldsm4(qh, sb + SM_Q + wid * 2304 + a_off + ko);
            ldsm4(ql, sb + SM_Q + 9216 + wid * 2304 + a_off + ko);
#pragma unroll
            for (int n16 = 0; n16 < 4; n16++) {
                uint32_t kb[4], kl2[4];
                ldsm4(kb,  stg + ST_KH + b_off + n16 * 2304 + ko);
                ldsm4(kl2, stg + ST_KL + b_off + n16 * 2304 + ko);
#pragma unroll
                for (int sub = 0; sub < 2; sub++) {
                    const int nf = n16 * 2 + sub;
                    mma16816(cQK[nf], qh, &kb[sub * 2]);
                    mma16816(cQK[nf], qh, &kl2[sub * 2]);
                    mma16816(cQK[nf], ql, &kb[sub * 2]);
                }
            }
#pragma unroll
            for (int n16 = 0; n16 < 8; n16++) {
                uint32_t pb[4], pl2[4];
                ldsm4(pb,  stg + ST_PH + b_off + n16 * 2304 + ko);
                ldsm4(pl2, stg + ST_PL + b_off + n16 * 2304 + ko);
#pragma unroll
                for (int sub = 0; sub < 2; sub++) {
                    const int nf = n16 * 2 + sub;
                    mma16816(cQP[nf], qh, &pb[sub * 2]);
                    mma16816(cQP[nf], qh, &pl2[sub * 2]);
                    mma16816(cQP[nf], ql, &pb[sub * 2]);
                }
            }
        }

        // spill QP to smem for the Toeplitz gather (warp-local rows)
        float* QPs = (float*)(smem + SM_QPS);
#pragma unroll
        for (int nf = 0; nf < 16; nf++) {
            int j0 = nf * 8 + colbase;
            *(float2*)&QPs[r0 * 132 + j0]       = make_float2(cQP[nf][0], cQP[nf][1]);
            *(float2*)&QPs[(r0 + 8) * 132 + j0] = make_float2(cQP[nf][2], cQP[nf][3]);
        }
        __syncwarp();

        // -------- logits + online softmax --------
        const float* ubS = (const float*)(smem + SM_ST + s * ST_SIZE + ST_UB);
        const float* bvS = (const float*)(smem + SM_ST + s * ST_SIZE + ST_BV);
        const int p0 = 63 - r0;
        const int p1 = 55 - r0;      // 63 - (r0+8)
        float tm0 = -1e30f, tm1 = -1e30f;
#pragma unroll
        for (int nf = 0; nf < 8; nf++) {
            int j0 = nf * 8 + colbase, j1 = j0 + 1;
            float v0 = (cQK[nf][0] + QPs[r0 * 132 + j0 + p0] + ubS[j0] + bvS[j0 + p0]) * 0.125f;
            float v1 = (cQK[nf][1] + QPs[r0 * 132 + j1 + p0] + ubS[j1] + bvS[j1 + p0]) * 0.125f;
            float v2 = (cQK[nf][2] + QPs[(r0 + 8) * 132 + j0 + p1] + ubS[j0] + bvS[j0 + p1]) * 0.125f;
            float v3 = (cQK[nf][3] + QPs[(r0 + 8) * 132 + j1 + p1] + ubS[j1] + bvS[j1 + p1]) * 0.125f;
            if (zt == st) {
                if (j0 > r0) v0 = -1e30f;
                if (j1 > r0) v1 = -1e30f;
                if (j0 > r0 + 8) v2 = -1e30f;
                if (j1 > r0 + 8) v3 = -1e30f;
            }
            cQK[nf][0] = v0; cQK[nf][1] = v1; cQK[nf][2] = v2; cQK[nf][3] = v3;
            tm0 = fmaxf(tm0, fmaxf(v0, v1));
            tm1 = fmaxf(tm1, fmaxf(v2, v3));
        }
        tm0 = fmaxf(tm0, __shfl_xor_sync(0xffffffffu, tm0, 1));
        tm0 = fmaxf(tm0, __shfl_xor_sync(0xffffffffu, tm0, 2));
        tm1 = fmaxf(tm1, __shfl_xor_sync(0xffffffffu, tm1, 1));
        tm1 = fmaxf(tm1, __shfl_xor_sync(0xffffffffu, tm1, 2));

        float nm0 = fmaxf(mrow[0], tm0), nm1 = fmaxf(mrow[1], tm1);
        float sc0 = __expf(mrow[0] - nm0), sc1 = __expf(mrow[1] - nm1);

        __nv_bfloat16* phs = (__nv_bfloat16*)(smem + SM_PRB);
        __nv_bfloat16* pls = (__nv_bfloat16*)(smem + SM_PRB + 9216);
        float ps0 = 0.f, ps1 = 0.f;
#pragma unroll
        for (int nf = 0; nf < 8; nf++) {
            int j0 = nf * 8 + colbase;
            float e0 = __expf(cQK[nf][0] - nm0);
            float e1 = __expf(cQK[nf][1] - nm0);
            float e2 = __expf(cQK[nf][2] - nm1);
            float e3 = __expf(cQK[nf][3] - nm1);
            ps0 += e0 + e1;
            ps1 += e2 + e3;
            __nv_bfloat16 h0 = __float2bfloat16(e0), h1 = __float2bfloat16(e1);
            __nv_bfloat16 h2 = __float2bfloat16(e2), h3 = __float2bfloat16(e3);
            __nv_bfloat162 hv, lv;
            hv.x = h0; hv.y = h1;
            lv.x = __float2bfloat16(e0 - __bfloat162float(h0));
            lv.y = __float2bfloat16(e1 - __bfloat162float(h1));
            *(__nv_bfloat162*)&phs[r0 * 72 + j0] = hv;
            *(__nv_bfloat162*)&pls[r0 * 72 + j0] = lv;
            hv.x = h2; hv.y = h3;
            lv.x = __float2bfloat16(e2 - __bfloat162float(h2));
            lv.y = __float2bfloat16(e3 - __bfloat162float(h3));
            *(__nv_bfloat162*)&phs[(r0 + 8) * 72 + j0] = hv;
            *(__nv_bfloat162*)&pls[(r0 + 8) * 72 + j0] = lv;
        }
        ps0 += __shfl_xor_sync(0xffffffffu, ps0, 1);
        ps0 += __shfl_xor_sync(0xffffffffu, ps0, 2);
        ps1 += __shfl_xor_sync(0xffffffffu, ps1, 1);
        ps1 += __shfl_xor_sync(0xffffffffu, ps1, 2);
        lsum[0] = lsum[0] * sc0 + ps0;
        lsum[1] = lsum[1] * sc1 + ps1;
        mrow[0] = nm0; mrow[1] = nm1;

#pragma unroll
        for (int nf = 0; nf < 8; nf++) {
            cO[nf][0] *= sc0; cO[nf][1] *= sc0;
            cO[nf][2] *= sc1; cO[nf][3] *= sc1;
        }
        __syncwarp();

        // -------- PV MMA (probs x V), bf16x3 --------
#pragma unroll
        for (int k16 = 0; k16 < 4; k16++) {
            const int ko = k16 * 32;
            uint32_t aph[4], apl[4];
            ldsm4(aph, sb + SM_PRB + wid * 2304 + a_off + ko);
            ldsm4(apl, sb + SM_PRB + 9216 + wid * 2304 + a_off + ko);
#pragma unroll
            for (int n16 = 0; n16 < 4; n16++) {
                uint32_t vb[4], vl2[4];
                ldsm4t(vb,  stg + ST_VH + a_off + k16 * 2304 + n16 * 32);
                ldsm4t(vl2, stg + ST_VL + a_off + k16 * 2304 + n16 * 32);
#pragma unroll
                for (int sub = 0; sub < 2; sub++) {
                    const int nf = n16 * 2 + sub;
                    mma16816(cO[nf], aph, &vb[sub * 2]);
                    mma16816(cO[nf], aph, &vl2[sub * 2]);
                    mma16816(cO[nf], apl, &vb[sub * 2]);
                }
            }
        }
    }

    // -------- output: bf16 hi/lo pairs --------
    const float i0 = 1.f / lsum[0];
    const float i1 = 1.f / lsum[1];
    const size_t row0 = (size_t)(b * S + s0 + r0);
    const size_t row1 = row0 + 8;
#pragma unroll
    for (int nf = 0; nf < 8; nf++) {
        int col = h * DK + nf * 8 + colbase;
        float o0 = cO[nf][0] * i0, o1 = cO[nf][1] * i0;
        float o2 = cO[nf][2] * i1, o3 = cO[nf][3] * i1;
        __nv_bfloat16 h0 = __float2bfloat16(o0), h1 = __float2bfloat16(o1);
        __nv_bfloat16 h2 = __float2bfloat16(o2), h3 = __float2bfloat16(o3);
        __nv_bfloat162 hv, lv;
        hv.x = h0; hv.y = h1;
        lv.x = __float2bfloat16(o0 - __bfloat162float(h0));
        lv.y = __float2bfloat16(o1 - __bfloat162float(h1));
        *(__nv_bfloat162*)(Oh + row0 * D + col) = hv;
        *(__nv_bfloat162*)(Ol + row0 * D + col) = lv;
        hv.x = h2; hv.y = h3;
        lv.x = __float2bfloat16(o2 - __bfloat162float(h2));
        lv.y = __float2bfloat16(o3 - __bfloat162float(h3));
        *(__nv_bfloat162*)(Oh + row1 * D + col) = hv;
        *(__nv_bfloat162*)(Ol + row1 * D + col) = lv;
    }
}

// ---------------------------------------------------------------------------
// Launch
// ---------------------------------------------------------------------------
extern "C" void kernel_launch(void* const* d_in, const int* in_sizes, int n_in,
                              void* d_out, int out_size)
{
    const float* x      = (const float*)d_in[0];
    const float* Wq     = (const float*)d_in[1];
    const float* bq     = (const float*)d_in[2];
    const float* Wk     = (const float*)d_in[3];
    const float* bk     = (const float*)d_in[4];
    const float* Wv     = (const float*)d_in[5];
    const float* bv     = (const float*)d_in[6];
    const float* Wr     = (const float*)d_in[7];
    const float* br     = (const float*)d_in[8];
    const float* rel_u  = (const float*)d_in[9];
    const float* rel_v  = (const float*)d_in[10];
    const float* Wo     = (const float*)d_in[11];
    const float* bo     = (const float*)d_in[12];
    const float* relpos = (const float*)d_in[13];
    float* out = (float*)d_out;

    float *KRb, *PRb, *ubb, *bvb;
    cudaGetSymbolAddress((void**)&KRb, g_KR);
    cudaGetSymbolAddress((void**)&PRb, g_PR);
    cudaGetSymbolAddress((void**)&ubb, g_ub);
    cudaGetSymbolAddress((void**)&bvb, g_Bv);

    __nv_bfloat16 *xh, *xl, *Rh, *Rl, *Wsh, *Wsl, *vh, *vl;
    __nv_bfloat16 *Qbh, *Qbl, *Kbh, *Kbl, *Vbh, *Vbl, *Pbh, *Pbl;
    cudaGetSymbolAddress((void**)&xh,  g_xh);
    cudaGetSymbolAddress((void**)&xl,  g_xl);
    cudaGetSymbolAddress((void**)&Rh,  g_Rh);
    cudaGetSymbolAddress((void**)&Rl,  g_Rl);
    cudaGetSymbolAddress((void**)&Wsh, g_Wsh);
    cudaGetSymbolAddress((void**)&Wsl, g_Wsl);
    cudaGetSymbolAddress((void**)&vh,  g_vh);
    cudaGetSymbolAddress((void**)&vl,  g_vl);
    cudaGetSymbolAddress((void**)&Qbh, g_Qbh);
    cudaGetSymbolAddress((void**)&Qbl, g_Qbl);
    cudaGetSymbolAddress((void**)&Kbh, g_Kbh);
    cudaGetSymbolAddress((void**)&Kbl, g_Kbl);
    cudaGetSymbolAddress((void**)&Vbh, g_Vbh);
    cudaGetSymbolAddress((void**)&Vbl, g_Vbl);
    cudaGetSymbolAddress((void**)&Pbh, g_Pbh);
    cudaGetSymbolAddress((void**)&Pbl, g_Pbl);

    const float* R = relpos + (size_t)1 * D;   // rows [1, 2048), L = 2047

    // --- splits ---
    split_kernel<<<(BS * D + 255) / 256, 256>>>(x, xh, xl, BS * D);
    const float* Ws[5] = {Wq, Wk, Wv, Wr, Wo};
    for (int i = 0; i < 5; i++)
        split_kernel<<<(D * D + 255) / 256, 256>>>(Ws[i], Wsh + (size_t)i * D * D,
                                                   Wsl + (size_t)i * D * D, D * D);
    split_kernel<<<(L * D + 255) / 256, 256>>>(R, Rh, Rl, L * D);

    cudaFuncSetAttribute(gemm_tc, cudaFuncAttributeMaxDynamicSharedMemorySize,
                         GEMM_SMEM);

    // --- Q/K/V/KR projections (batched, grid.z = 4) ---
    GemmBatch b1 = {};
    b1.Wh[0] = Wsh + 0 * (size_t)D * D; b1.Wl[0] = Wsl + 0 * (size_t)D * D;
    b1.bias[0] = bq; b1.mode[0] = 1; b1.Ch[0] = Qbh; b1.Cl[0] = Qbl;
    b1.Wh[1] = Wsh + 1 * (size_t)D * D; b1.Wl[1] = Wsl + 1 * (size_t)D * D;
    b1.bias[1] = bk; b1.mode[1] = 1; b1.Ch[1] = Kbh; b1.Cl[1] = Kbl;
    b1.Wh[2] = Wsh + 2 * (size_t)D * D; b1.Wl[2] = Wsl + 2 * (size_t)D * D;
    b1.bias[2] = bv; b1.mode[2] = 1; b1.Ch[2] = Vbh; b1.Cl[2] = Vbl;
    b1.Wh[3] = Wsh + 3 * (size_t)D * D; b1.Wl[3] = Wsl + 3 * (size_t)D * D;
    b1.bias[3] = br; b1.mode[3] = 0; b1.C[3] = KRb;
    gemm_tc<<<dim3(8, 32, 4), 256, GEMM_SMEM>>>(xh, xl, b1, BS);

    // --- P/PR projections (batched, grid.z = 2) ---
    GemmBatch b2 = {};
    b2.Wh[0] = Wsh + 1 * (size_t)D * D; b2.Wl[0] = Wsl + 1 * (size_t)D * D;
    b2.bias[0] = bk; b2.mode[0] = 1; b2.Ch[0] = Pbh; b2.Cl[0] = Pbl;
    b2.Wh[1] = Wsh + 3 * (size_t)D * D; b2.Wl[1] = Wsl + 3 * (size_t)D * D;
    b2.bias[1] = br; b2.mode[1] = 0; b2.C[1] = PRb;
    b2.Wh[2] = b2.Wh[0]; b2.Wl[2] = b2.Wl[0]; b2.bias[2] = bk; b2.mode[2] = 0; b2.C[2] = PRb;
    b2.Wh[3] = b2.Wh[0]; b2.Wl[3] = b2.Wl[0]; b2.bias[3] = bk; b2.mode[3] = 0; b2.C[3] = PRb;
    gemm_tc<<<dim3(8, 16, 2), 256, GEMM_SMEM>>>(Rh, Rl, b2, L);

    ubias_kernel<<<(B * H * S + 255) / 256, 256>>>(KRb, rel_u, ubb);
    bv_kernel<<<(H * L + 255) / 256, 256>>>(PRb, rel_v, bvb);

    // --- tensorized attention ---
    cudaFuncSetAttribute(attn_mma, cudaFuncAttributeMaxDynamicSharedMemorySize,
                         ATTN_SMEM_BYTES);
    attn_mma<<<dim3(S / 64, B * H), 128, ATTN_SMEM_BYTES>>>(
        Qbh, Qbl, Kbh, Kbl, Vbh, Vbl, Pbh, Pbl, ubb, bvb, vh, vl);

    // --- output projection (fp32 out) ---
    GemmBatch b3 = {};
    b3.Wh[0] = Wsh + 4 * (size_t)D * D; b3.Wl[0] = Wsl + 4 * (size_t)D * D;
    b3.bias[0] = bo; b3.mode[0] = 0; b3.C[0] = out;
    b3.Wh[1] = b3.Wh[0]; b3.Wl[1] = b3.Wl[0]; b3.bias[1] = bo; b3.mode[1] = 0; b3.C[1] = out;
    b3.Wh[2] = b3.Wh[0]; b3.Wl[2] = b3.Wl[0]; b3.bias[2] = bo; b3.mode[2] = 0; b3.C[2] = out;
    b3.Wh[3] = b3.Wh[0]; b3.Wl[3] = b3.Wl[0]; b3.bias[3] = bo; b3.mode[3] = 0; b3.C[3] = out;
    gemm_tc<<<dim3(8, 32, 1), 256, GEMM_SMEM>>>(vh, vl, b3, BS);
}

// round 8
// speedup vs baseline: 4.4360x; 1.2260x over previous
#include <cuda_runtime.h>
#include <cuda_bf16.h>
#include <cstdint>

// Problem constants
#define B 4
#define S 1024
#define D 1024
#define H 16
#define DK 64
#define L 2047          // 2*S - 1
#define LP 1088         // P/PR rows actually used by attention (max read 1086)
#define BS (B*S)        // 4096

// ---------------------------------------------------------------------------
// Scratch (static device globals; no runtime allocation allowed)
// ---------------------------------------------------------------------------
__device__ float g_KR[BS * D];
__device__ float g_PR[L * D];
__device__ float g_ub[B * H * S];
__device__ float g_Bv[H * L];

// bf16 hi/lo splits (inputs to tensor-core GEMMs)
__device__ __nv_bfloat16 g_xh[BS * D], g_xl[BS * D];
__device__ __nv_bfloat16 g_Rh[L * D],  g_Rl[L * D];
__device__ __nv_bfloat16 g_Wsh[5 * D * D], g_Wsl[5 * D * D];   // q,k,v,r,o

// bf16 hi/lo GEMM outputs (attention inputs)
__device__ __nv_bfloat16 g_Qbh[BS * D], g_Qbl[BS * D];
__device__ __nv_bfloat16 g_Kbh[BS * D], g_Kbl[BS * D];
__device__ __nv_bfloat16 g_Vbh[BS * D], g_Vbl[BS * D];
__device__ __nv_bfloat16 g_Pbh[L * D],  g_Pbl[L * D];

// attention output (bf16 pairs; input to out-projection)
__device__ __nv_bfloat16 g_vh[BS * D], g_vl[BS * D];

// ---------------------------------------------------------------------------
// PTX helpers: portable sm_80+ (ldmatrix / mma.sync / cp.async).
// ---------------------------------------------------------------------------
__device__ __forceinline__ uint32_t smem_to_u32(const void* p) {
    uint32_t a;
    asm("{ .reg .u64 t; cvta.to.shared.u64 t, %1; cvt.u32.u64 %0, t; }"
        : "=r"(a) : "l"(p));
    return a;
}

__device__ __forceinline__ void ldsm4(uint32_t* r, uint32_t addr) {
    asm volatile("ldmatrix.sync.aligned.m8n8.x4.shared.b16 {%0,%1,%2,%3}, [%4];"
                 : "=r"(r[0]), "=r"(r[1]), "=r"(r[2]), "=r"(r[3]) : "r"(addr));
}
__device__ __forceinline__ void ldsm4t(uint32_t* r, uint32_t addr) {
    asm volatile("ldmatrix.sync.aligned.m8n8.x4.trans.shared.b16 {%0,%1,%2,%3}, [%4];"
                 : "=r"(r[0]), "=r"(r[1]), "=r"(r[2]), "=r"(r[3]) : "r"(addr));
}

__device__ __forceinline__ void mma16816(float* d, const uint32_t* a,
                                         const uint32_t* b) {
    asm volatile(
        "mma.sync.aligned.m16n8k16.row.col.f32.bf16.bf16.f32 "
        "{%0,%1,%2,%3}, {%4,%5,%6,%7}, {%8,%9}, {%0,%1,%2,%3};"
        : "+f"(d[0]), "+f"(d[1]), "+f"(d[2]), "+f"(d[3])
        : "r"(a[0]), "r"(a[1]), "r"(a[2]), "r"(a[3]), "r"(b[0]), "r"(b[1]));
}

__device__ __forceinline__ void cp16(uint32_t dst, const void* src, int sz) {
    asm volatile("cp.async.cg.shared.global [%0], [%1], 16, %2;\n"
                 :: "r"(dst), "l"(src), "r"(sz));
}
__device__ __forceinline__ void cp_commit() {
    asm volatile("cp.async.commit_group;\n" ::: "memory");
}
template <int N> __device__ __forceinline__ void cp_wait() {
    asm volatile("cp.async.wait_group %0;\n" :: "n"(N) : "memory");
}

// ---------------------------------------------------------------------------
// fp32 -> bf16 hi/lo splits
// ---------------------------------------------------------------------------
__global__ void split_kernel(const float* __restrict__ s,
                             __nv_bfloat16* __restrict__ hi,
                             __nv_bfloat16* __restrict__ lo, int n)
{
    int i = blockIdx.x * 256 + threadIdx.x;
    if (i < n) {
        float x = s[i];
        __nv_bfloat16 h = __float2bfloat16(x);
        float r = x - __bfloat162float(h);
        hi[i] = h;
        lo[i] = __float2bfloat16(r);
    }
}

struct SplitBatch { const float* src[5]; };

__global__ void splitW_kernel(const SplitBatch sb,
                              __nv_bfloat16* __restrict__ hi,
                              __nv_bfloat16* __restrict__ lo)
{
    int z = blockIdx.y;
    int i = blockIdx.x * 256 + threadIdx.x;
    size_t off = (size_t)z * D * D + i;
    float x = sb.src[z][i];
    __nv_bfloat16 h = __float2bfloat16(x);
    hi[off] = h;
    lo[off] = __float2bfloat16(x - __bfloat162float(h));
}

// ---------------------------------------------------------------------------
// HMMA GEMM: C[M,1024] = A[M,1024] @ W[1024,1024]^T + bias
// bf16x3 compensation. mode 0: fp32 C;  mode 1: bf16 hi/lo pair outputs.
// z < 4: A = (Ah1, Al1), M = M1.  z >= 4: A = (Ah2, Al2), M = M2.
// 2 CTAs/SM, single barrier per K-chunk.
// ---------------------------------------------------------------------------
struct GemmBatch {
    const __nv_bfloat16* Wh[6];
    const __nv_bfloat16* Wl[6];
    const float* bias[6];
    float* C[6];
    __nv_bfloat16* Ch[6];
    __nv_bfloat16* Cl[6];
    int mode[6];
};

#define RS      40                   // bf16 elems per smem row (80 bytes)
#define TILE_B  (128 * RS * 2)       // 10240 B
#define STAGE_B (4 * TILE_B)
#define GEMM_SMEM (2 * STAGE_B)      // 81920
#define NC      32

__device__ __forceinline__ void load_chunk(
    uint32_t sbase, int tid,
    const __nv_bfloat16* Ah, const __nv_bfloat16* Al,
    const __nv_bfloat16* Wh, const __nv_bfloat16* Wl,
    int bm, int bn, int M, int c, int st)
{
    const int kbase = c * 32;
    const uint32_t stoff = sbase + st * STAGE_B;
#pragma unroll
    for (int t = 0; t < 4; t++) {
        const __nv_bfloat16* base = (t == 0) ? Ah : (t == 1) ? Al : (t == 2) ? Wh : Wl;
        const int rb = (t < 2) ? bm : bn;
#pragma unroll
        for (int j = 0; j < 2; j++) {
            int idx = tid + j * 256;
            int row = idx >> 2, g = idx & 3;
            int gr = rb + row;
            int sz = (t >= 2 || gr < M) ? 16 : 0;
            const void* src = base + (size_t)gr * 1024 + kbase + g * 8;
            uint32_t dst = stoff + t * TILE_B + row * 80 + g * 16;
            cp16(dst, src, sz);
        }
    }
}

__global__ __launch_bounds__(256, 2)
void gemm_tc(const __nv_bfloat16* __restrict__ Ah1,
             const __nv_bfloat16* __restrict__ Al1,
             const __nv_bfloat16* __restrict__ Ah2,
             const __nv_bfloat16* __restrict__ Al2,
             const GemmBatch bat, int M1, int M2)
{
    extern __shared__ char smem[];
    const uint32_t sbase = smem_to_u32(smem);
    const int tid  = threadIdx.x;
    const int wid  = tid >> 5;
    const int lane = tid & 31;
    const int bn = blockIdx.x * 128;
    const int bm = blockIdx.y * 128;
    const int z  = blockIdx.z;

    const __nv_bfloat16* Ah = (z < 4) ? Ah1 : Ah2;
    const __nv_bfloat16* Al = (z < 4) ? Al1 : Al2;
    const int M = (z < 4) ? M1 : M2;
    if (bm >= M) return;               // early-exit tail tiles (P/PR trim)

    const __nv_bfloat16* Wh = bat.Wh[z];
    const __nv_bfloat16* Wl = bat.Wl[z];

    const int mb = (wid >> 2) * 64;
    const int nb = (wid & 3) * 32;

    const int li = lane >> 3, lr = lane & 7;
    const int a_off = ((li & 1) * 8 + lr) * 80 + (li >> 1) * 16;
    const int b_off = ((li >> 1) * 8 + lr) * 80 + (li & 1) * 16;

    float acc[4][4][4];
#pragma unroll
    for (int mf = 0; mf < 4; mf++)
#pragma unroll
        for (int nf = 0; nf < 4; nf++)
#pragma unroll
            for (int e = 0; e < 4; e++) acc[mf][nf][e] = 0.f;

    load_chunk(sbase, tid, Ah, Al, Wh, Wl, bm, bn, M, 0, 0);
    cp_commit();

    for (int c = 0; c < NC; c++) {
        const int st = c & 1;
        cp_wait<0>();                  // chunk c resident
        __syncthreads();               // all warps done with mma of c-1
        if (c + 1 < NC) {
            load_chunk(sbase, tid, Ah, Al, Wh, Wl, bm, bn, M, c + 1, st ^ 1);
            cp_commit();
        }

        const uint32_t aH = sbase + st * STAGE_B + 0 * TILE_B + (mb)*80 + a_off;
        const uint32_t aL = aH + TILE_B;
        const uint32_t wH = sbase + st * STAGE_B + 2 * TILE_B + (nb)*80 + b_off;
        const uint32_t wL = wH + TILE_B;

#pragma unroll
        for (int k16 = 0; k16 < 2; k16++) {
            const int ko = k16 * 32;
            uint32_t ah[4][4], al[4][4], bh[2][4], bl[2][4];
#pragma unroll
            for (int mf = 0; mf < 4; mf++) {
                ldsm4(ah[mf], aH + mf * 16 * 80 + ko);
                ldsm4(al[mf], aL + mf * 16 * 80 + ko);
            }
#pragma unroll
            for (int n2 = 0; n2 < 2; n2++) {
                ldsm4(bh[n2], wH + n2 * 16 * 80 + ko);
                ldsm4(bl[n2], wL + n2 * 16 * 80 + ko);
            }
#pragma unroll
            for (int mf = 0; mf < 4; mf++)
#pragma unroll
                for (int nf = 0; nf < 4; nf++) {
                    const uint32_t* bph = &bh[nf >> 1][(nf & 1) * 2];
                    const uint32_t* bpl = &bl[nf >> 1][(nf & 1) * 2];
                    mma16816(acc[mf][nf], ah[mf], bph);
                    mma16816(acc[mf][nf], ah[mf], bpl);
                    mma16816(acc[mf][nf], al[mf], bph);
                }
        }
    }

    const float* bias = bat.bias[z];
    const int lr4 = lane >> 2, lc2 = (lane & 3) * 2;
    if (bat.mode[z] == 0) {
        float* C = bat.C[z];
#pragma unroll
        for (int mf = 0; mf < 4; mf++)
#pragma unroll
            for (int nf = 0; nf < 4; nf++) {
                int gn = bn + nb + nf * 8 + lc2;
                float2 bi = *(const float2*)(bias + gn);
                int gm0 = bm + mb + mf * 16 + lr4;
                if (gm0 < M) {
                    float2 v = make_float2(acc[mf][nf][0] + bi.x, acc[mf][nf][1] + bi.y);
                    *(float2*)(C + (size_t)gm0 * 1024 + gn) = v;
                }
                int gm1 = gm0 + 8;
                if (gm1 < M) {
                    float2 v = make_float2(acc[mf][nf][2] + bi.x, acc[mf][nf][3] + bi.y);
                    *(float2*)(C + (size_t)gm1 * 1024 + gn) = v;
                }
            }
    } else {
        __nv_bfloat16* Ch = bat.Ch[z];
        __nv_bfloat16* Cl = bat.Cl[z];
#pragma unroll
        for (int mf = 0; mf < 4; mf++)
#pragma unroll
            for (int nf = 0; nf < 4; nf++) {
                int gn = bn + nb + nf * 8 + lc2;
                float2 bi = *(const float2*)(bias + gn);
#pragma unroll
                for (int half = 0; half < 2; half++) {
                    int gm = bm + mb + mf * 16 + lr4 + half * 8;
                    if (gm < M) {
                        float vx = acc[mf][nf][half * 2 + 0] + bi.x;
                        float vy = acc[mf][nf][half * 2 + 1] + bi.y;
                        __nv_bfloat16 hx = __float2bfloat16(vx);
                        __nv_bfloat16 hy = __float2bfloat16(vy);
                        __nv_bfloat162 hv; hv.x = hx; hv.y = hy;
                        __nv_bfloat162 lv;
                        lv.x = __float2bfloat16(vx - __bfloat162float(hx));
                        lv.y = __float2bfloat16(vy - __bfloat162float(hy));
                        *(__nv_bfloat162*)(Ch + (size_t)gm * 1024 + gn) = hv;
                        *(__nv_bfloat162*)(Cl + (size_t)gm * 1024 + gn) = lv;
                    }
                }
            }
    }
}

// ---------------------------------------------------------------------------
// ubias / Bv reductions (fp32 inputs)
// ---------------------------------------------------------------------------
__global__ void ubias_kernel(const float* __restrict__ KR,
                             const float* __restrict__ rel_u,
                             float* __restrict__ ub)
{
    int idx = blockIdx.x * 256 + threadIdx.x;
    if (idx >= B * H * S) return;
    int z = idx & (S - 1);
    int h = (idx >> 10) & (H - 1);
    int b = idx >> 14;
    const float* kr = KR + ((size_t)(b * S + z)) * D + h * DK;
    const float* ru = rel_u + h * DK;
    float s = 0.f;
#pragma unroll
    for (int d = 0; d < DK; d++) s = fmaf(kr[d], ru[d], s);
    ub[idx] = s;
}

__global__ void bv_kernel(const float* __restrict__ PR,
                          const float* __restrict__ rel_v,
                          float* __restrict__ Bv)
{
    int idx = blockIdx.x * 256 + threadIdx.x;
    if (idx >= H * LP) return;
    int l = idx % LP;
    int h = idx / LP;
    const float* pr = PR + (size_t)l * D + h * DK;
    const float* rv = rel_v + h * DK;
    float s = 0.f;
#pragma unroll
    for (int d = 0; d < DK; d++) s = fmaf(pr[d], rv[d], s);
    Bv[h * L + l] = s;
}

// ---------------------------------------------------------------------------
// Tensorized fused relative attention (flash-style, causal, bf16x3 MMA).
// CTA: 64 q-rows, 4 warps. Grid (bh, tiles) with heavy tiles scheduled first.
// ---------------------------------------------------------------------------
#define ATS      144                 // smem row stride bytes (72 bf16)
#define ST_KH    0
#define ST_KL    9216
#define ST_VH    18432
#define ST_VL    27648
#define ST_PH    36864               // 128 rows
#define ST_PL    55296
#define ST_UB    73728               // 64 floats
#define ST_BV    73984               // 127 floats (+pad)
#define ST_SIZE  74496
#define SM_Q     0                   // Qh 9216, Ql 9216
#define SM_ST    18432
#define SM_QPS   (18432 + 2 * ST_SIZE)          // fp32 64 x 132
#define SM_PRB   (SM_QPS + 33792)               // phs 9216, pls 9216
#define ATTN_SMEM_BYTES (SM_PRB + 18432)        // 219648

__device__ __forceinline__ void attn_load_stage(
    uint32_t stg, int tid,
    const __nv_bfloat16* Kh, const __nv_bfloat16* Kl,
    const __nv_bfloat16* Vh, const __nv_bfloat16* Vl,
    const __nv_bfloat16* Ph, const __nv_bfloat16* Pl)
{
#pragma unroll
    for (int j = 0; j < 4; j++) {
        int idx = tid + j * 128;
        int row = idx >> 3, g = idx & 7;
        const size_t go = (size_t)row * D + g * 8;
        uint32_t so = row * ATS + g * 16;
        cp16(stg + ST_KH + so, Kh + go, 16);
        cp16(stg + ST_KL + so, Kl + go, 16);
        cp16(stg + ST_VH + so, Vh + go, 16);
        cp16(stg + ST_VL + so, Vl + go, 16);
    }
#pragma unroll
    for (int j = 0; j < 8; j++) {
        int idx = tid + j * 128;
        if (idx < 1016) {                       // 127 rows x 8 segs
            int row = idx >> 3, g = idx & 7;
            const size_t go = (size_t)row * D + g * 8;
            uint32_t so = row * ATS + g * 16;
            cp16(stg + ST_PH + so, Ph + go, 16);
            cp16(stg + ST_PL + so, Pl + go, 16);
        }
    }
}

__global__ __launch_bounds__(128, 1) void attn_mma(
    const __nv_bfloat16* __restrict__ Qh, const __nv_bfloat16* __restrict__ Ql,
    const __nv_bfloat16* __restrict__ Kh, const __nv_bfloat16* __restrict__ Kl,
    const __nv_bfloat16* __restrict__ Vh, const __nv_bfloat16* __restrict__ Vl,
    const __nv_bfloat16* __restrict__ Ph, const __nv_bfloat16* __restrict__ Pl,
    const float* __restrict__ ubias, const float* __restrict__ Bv,
    __nv_bfloat16* __restrict__ Oh, __nv_bfloat16* __restrict__ Ol)
{
    extern __shared__ char smem[];
    const uint32_t sb = smem_to_u32(smem);
    const int tid  = threadIdx.x;
    const int wid  = tid >> 5;
    const int lane = tid & 31;
    const int st = (S / 64 - 1) - blockIdx.y;    // heavy tiles first
    const int b  = blockIdx.x >> 4;
    const int h  = blockIdx.x & 15;
    const int s0 = st * 64;

    const int li = lane >> 3, lr = lane & 7;
    const int a_off = ((li & 1) * 8 + lr) * ATS + (li >> 1) * 16;
    const int b_off = ((li >> 1) * 8 + lr) * ATS + (li & 1) * 16;

    const int r0 = wid * 16 + (lane >> 2);
    const int colbase = (lane & 3) * 2;

    // -------- prologue: Q tile + stage 0 --------
    {
        const __nv_bfloat16* Qgh = Qh + (size_t)(b * S + s0) * D + h * DK;
        const __nv_bfloat16* Qgl = Ql + (size_t)(b * S + s0) * D + h * DK;
#pragma unroll
        for (int j = 0; j < 4; j++) {
            int idx = tid + j * 128;
            int row = idx >> 3, g = idx & 7;
            const size_t go = (size_t)row * D + g * 8;
            uint32_t so = row * ATS + g * 16;
            cp16(sb + SM_Q + so, Qgh + go, 16);
            cp16(sb + SM_Q + 9216 + so, Qgl + go, 16);
        }
        const size_t kvoff = (size_t)(b * S) * D + h * DK;
        int lbase0 = -st * 64 + 960;
        attn_load_stage(sb + SM_ST, tid,
                        Kh + kvoff, Kl + kvoff, Vh + kvoff, Vl + kvoff,
                        Ph + (size_t)lbase0 * D + h * DK,
                        Pl + (size_t)lbase0 * D + h * DK);
        float* ubS = (float*)(smem + SM_ST + ST_UB);
        float* bvS = (float*)(smem + SM_ST + ST_BV);
        if (tid < 64)  ubS[tid] = ubias[(b * H + h) * S + tid];
        if (tid < 127) bvS[tid] = Bv[h * L + lbase0 + tid];
        cp_commit();
    }

    float cO[8][4];
#pragma unroll
    for (int nf = 0; nf < 8; nf++)
#pragma unroll
        for (int e = 0; e < 4; e++) cO[nf][e] = 0.f;
    float mrow[2] = {-1e30f, -1e30f};
    float lsum[2] = {0.f, 0.f};

    for (int zt = 0; zt <= st; zt++) {
        const int s = zt & 1;
        const uint32_t stg = sb + SM_ST + s * ST_SIZE;

        cp_wait<0>();
        __syncthreads();

        if (zt < st) {
            const int z1 = (zt + 1) * 64;
            const int lb1 = (zt + 1 - st) * 64 + 960;
            const size_t kvoff = (size_t)(b * S + z1) * D + h * DK;
            uint32_t nstg = sb + SM_ST + (s ^ 1) * ST_SIZE;
            attn_load_stage(nstg, tid,
                            Kh + kvoff, Kl + kvoff, Vh + kvoff, Vl + kvoff,
                            Ph + (size_t)lb1 * D + h * DK,
                            Pl + (size_t)lb1 * D + h * DK);
            float* ubS = (float*)(smem + SM_ST + (s ^ 1) * ST_SIZE + ST_UB);
            float* bvS = (float*)(smem + SM_ST + (s ^ 1) * ST_SIZE + ST_BV);
            if (tid < 64)  ubS[tid] = ubias[(b * H + h) * S + z1 + tid];
            if (tid < 127) bvS[tid] = Bv[h * L + lb1 + tid];
            cp_commit();
        }

        // -------- QP (64x128) and QK (64x64) MMA, bf16x3 --------
        float cQP[16][4], cQK[8][4];
#pragma unroll
        for (int nf = 0; nf < 16; nf++)
#pragma unroll
            for (int e = 0; e < 4; e++) cQP[nf][e] = 0.f;
#pragma unroll
        for (int nf = 0; nf < 8; nf++)
#pragma unroll
            for (int e = 0; e < 4; e++) cQK[nf][e] = 0.f;

#pragma unroll
        for (int k16 = 0; k16 < 4; k16++) {
            const int ko = k16 * 32;
            uint32_t qh[4], ql[4];
            ldsm4(qh, sb + SM_Q + wid * 2304 + a_off + ko);
            ldsm4(ql, sb + SM_Q + 9216 + wid * 2304 + a_off + ko);
#pragma unroll
            for (int n16 = 0; n16 < 4; n16++) {
                uint32_t kb[4], kl2[4];
                ldsm4(kb,  stg + ST_KH + b_off + n16 * 2304 + ko);
                ldsm4(kl2, stg + ST_KL + b_off + n16 * 2304 + ko);
#pragma unroll
                for (int sub = 0; sub < 2; sub++) {
                    const int nf = n16 * 2 + sub;
                    mma16816(cQK[nf], qh, &kb[sub * 2]);
                    mma16816(cQK[nf], qh, &kl2[sub * 2]);
                    mma16816(cQK[nf], ql, &kb[sub * 2]);
                }
            }
#pragma unroll
            for (int n16 = 0; n16 < 8; n16++) {
                uint32_t pb[4], pl2[4];
                ldsm4(pb,  stg + ST_PH + b_off + n16 * 2304 + ko);
                ldsm4(pl2, stg + ST_PL + b_off + n16 * 2304 + ko);
#pragma unroll
                for (int sub = 0; sub < 2; sub++) {
                    const int nf = n16 * 2 + sub;
                    mma16816(cQP[nf], qh, &pb[sub * 2]);
                    mma16816(cQP[nf], qh, &pl2[sub * 2]);
                    mma16816(cQP[nf], ql, &pb[sub * 2]);
                }
            }
        }

        // spill QP to smem for the Toeplitz gather (warp-local rows)
        float* QPs = (float*)(smem + SM_QPS);
#pragma unroll
        for (int nf = 0; nf < 16; nf++) {
            int j0 = nf * 8 + colbase;
            *(float2*)&QPs[r0 * 132 + j0]       = make_float2(cQP[nf][0], cQP[nf][1]);
            *(float2*)&QPs[(r0 + 8) * 132 + j0] = make_float2(cQP[nf][2], cQP[nf][3]);
        }
        __syncwarp();

        // -------- logits + online softmax --------
        const float* ubS = (const float*)(smem + SM_ST + s * ST_SIZE + ST_UB);
        const float* bvS = (const float*)(smem + SM_ST + s * ST_SIZE + ST_BV);
        const int p0 = 63 - r0;
        const int p1 = 55 - r0;
        float tm0 = -1e30f, tm1 = -1e30f;
#pragma unroll
        for (int nf = 0; nf < 8; nf++) {
            int j0 = nf * 8 + colbase, j1 = j0 + 1;
            float v0 = (cQK[nf][0] + QPs[r0 * 132 + j0 + p0] + ubS[j0] + bvS[j0 + p0]) * 0.125f;
            float v1 = (cQK[nf][1] + QPs[r0 * 132 + j1 + p0] + ubS[j1] + bvS[j1 + p0]) * 0.125f;
            float v2 = (cQK[nf][2] + QPs[(r0 + 8) * 132 + j0 + p1] + ubS[j0] + bvS[j0 + p1]) * 0.125f;
            float v3 = (cQK[nf][3] + QPs[(r0 + 8) * 132 + j1 + p1] + ubS[j1] + bvS[j1 + p1]) * 0.125f;
            if (zt == st) {
                if (j0 > r0) v0 = -1e30f;
                if (j1 > r0) v1 = -1e30f;
                if (j0 > r0 + 8) v2 = -1e30f;
                if (j1 > r0 + 8) v3 = -1e30f;
            }
            cQK[nf][0] = v0; cQK[nf][1] = v1; cQK[nf][2] = v2; cQK[nf][3] = v3;
            tm0 = fmaxf(tm0, fmaxf(v0, v1));
            tm1 = fmaxf(tm1, fmaxf(v2, v3));
        }
        tm0 = fmaxf(tm0, __shfl_xor_sync(0xffffffffu, tm0, 1));
        tm0 = fmaxf(tm0, __shfl_xor_sync(0xffffffffu, tm0, 2));
        tm1 = fmaxf(tm1, __shfl_xor_sync(0xffffffffu, tm1, 1));
        tm1 = fmaxf(tm1, __shfl_xor_sync(0xffffffffu, tm1, 2));

        float nm0 = fmaxf(mrow[0], tm0), nm1 = fmaxf(mrow[1], tm1);
        float sc0 = __expf(mrow[0] - nm0), sc1 = __expf(mrow[1] - nm1);

        __nv_bfloat16* phs = (__nv_bfloat16*)(smem + SM_PRB);
        __nv_bfloat16* pls = (__nv_bfloat16*)(smem + SM_PRB + 9216);
        float ps0 = 0.f, ps1 = 0.f;
#pragma unroll
        for (int nf = 0; nf < 8; nf++) {
            int j0 = nf * 8 + colbase;
            float e0 = __expf(cQK[nf][0] - nm0);
            float e1 = __expf(cQK[nf][1] - nm0);
            float e2 = __expf(cQK[nf][2] - nm1);
            float e3 = __expf(cQK[nf][3] - nm1);
            ps0 += e0 + e1;
            ps1 += e2 + e3;
            __nv_bfloat16 h0 = __float2bfloat16(e0), h1 = __float2bfloat16(e1);
            __nv_bfloat16 h2 = __float2bfloat16(e2), h3 = __float2bfloat16(e3);
            __nv_bfloat162 hv, lv;
            hv.x = h0; hv.y = h1;
            lv.x = __float2bfloat16(e0 - __bfloat162float(h0));
            lv.y = __float2bfloat16(e1 - __bfloat162float(h1));
            *(__nv_bfloat162*)&phs[r0 * 72 + j0] = hv;
            *(__nv_bfloat162*)&pls[r0 * 72 + j0] = lv;
            hv.x = h2; hv.y = h3;
            lv.x = __float2bfloat16(e2 - __bfloat162float(h2));
            lv.y = __float2bfloat16(e3 - __bfloat162float(h3));
            *(__nv_bfloat162*)&phs[(r0 + 8) * 72 + j0] = hv;
            *(__nv_bfloat162*)&pls[(r0 + 8) * 72 + j0] = lv;
        }
        ps0 += __shfl_xor_sync(0xffffffffu, ps0, 1);
        ps0 += __shfl_xor_sync(0xffffffffu, ps0, 2);
        ps1 += __shfl_xor_sync(0xffffffffu, ps1, 1);
        ps1 += __shfl_xor_sync(0xffffffffu, ps1, 2);
        lsum[0] = lsum[0] * sc0 + ps0;
        lsum[1] = lsum[1] * sc1 + ps1;
        mrow[0] = nm0; mrow[1] = nm1;

#pragma unroll
        for (int nf = 0; nf < 8; nf++) {
            cO[nf][0] *= sc0; cO[nf][1] *= sc0;
            cO[nf][2] *= sc1; cO[nf][3] *= sc1;
        }
        __syncwarp();

        // -------- PV MMA (probs x V), bf16x3 --------
#pragma unroll
        for (int k16 = 0; k16 < 4; k16++) {
            const int ko = k16 * 32;
            uint32_t aph[4], apl[4];
            ldsm4(aph, sb + SM_PRB + wid * 2304 + a_off + ko);
            ldsm4(apl, sb + SM_PRB + 9216 + wid * 2304 + a_off + ko);
#pragma unroll
            for (int n16 = 0; n16 < 4; n16++) {
                uint32_t vb[4], vl2[4];
                ldsm4t(vb,  stg + ST_VH + a_off + k16 * 2304 + n16 * 32);
                ldsm4t(vl2, stg + ST_VL + a_off + k16 * 2304 + n16 * 32);
#pragma unroll
                for (int sub = 0; sub < 2; sub++) {
                    const int nf = n16 * 2 + sub;
                    mma16816(cO[nf], aph, &vb[sub * 2]);
                    mma16816(cO[nf], aph, &vl2[sub * 2]);
                    mma16816(cO[nf], apl, &vb[sub * 2]);
                }
            }
        }
    }

    // -------- output: bf16 hi/lo pairs --------
    const float i0 = 1.f / lsum[0];
    const float i1 = 1.f / lsum[1];
    const size_t row0 = (size_t)(b * S + s0 + r0);
    const size_t row1 = row0 + 8;
#pragma unroll
    for (int nf = 0; nf < 8; nf++) {
        int col = h * DK + nf * 8 + colbase;
        float o0 = cO[nf][0] * i0, o1 = cO[nf][1] * i0;
        float o2 = cO[nf][2] * i1, o3 = cO[nf][3] * i1;
        __nv_bfloat16 h0 = __float2bfloat16(o0), h1 = __float2bfloat16(o1);
        __nv_bfloat16 h2 = __float2bfloat16(o2), h3 = __float2bfloat16(o3);
        __nv_bfloat162 hv, lv;
        hv.x = h0; hv.y = h1;
        lv.x = __float2bfloat16(o0 - __bfloat162float(h0));
        lv.y = __float2bfloat16(o1 - __bfloat162float(h1));
        *(__nv_bfloat162*)(Oh + row0 * D + col) = hv;
        *(__nv_bfloat162*)(Ol + row0 * D + col) = lv;
        hv.x = h2; hv.y = h3;
        lv.x = __float2bfloat16(o2 - __bfloat162float(h2));
        lv.y = __float2bfloat16(o3 - __bfloat162float(h3));
        *(__nv_bfloat162*)(Oh + row1 * D + col) = hv;
        *(__nv_bfloat162*)(Ol + row1 * D + col) = lv;
    }
}

// ---------------------------------------------------------------------------
// Launch
// ---------------------------------------------------------------------------
extern "C" void kernel_launch(void* const* d_in, const int* in_sizes, int n_in,
                              void* d_out, int out_size)
{
    const float* x      = (const float*)d_in[0];
    const float* Wq     = (const float*)d_in[1];
    const float* bq     = (const float*)d_in[2];
    const float* Wk     = (const float*)d_in[3];
    const float* bk     = (const float*)d_in[4];
    const float* Wv     = (const float*)d_in[5];
    const float* bv     = (const float*)d_in[6];
    const float* Wr     = (const float*)d_in[7];
    const float* br     = (const float*)d_in[8];
    const float* rel_u  = (const float*)d_in[9];
    const float* rel_v  = (const float*)d_in[10];
    const float* Wo     = (const float*)d_in[11];
    const float* bo     = (const float*)d_in[12];
    const float* relpos = (const float*)d_in[13];
    float* out = (float*)d_out;

    float *KRb, *PRb, *ubb, *bvb;
    cudaGetSymbolAddress((void**)&KRb, g_KR);
    cudaGetSymbolAddress((void**)&PRb, g_PR);
    cudaGetSymbolAddress((void**)&ubb, g_ub);
    cudaGetSymbolAddress((void**)&bvb, g_Bv);

    __nv_bfloat16 *xh, *xl, *Rh, *Rl, *Wsh, *Wsl, *vh, *vl;
    __nv_bfloat16 *Qbh, *Qbl, *Kbh, *Kbl, *Vbh, *Vbl, *Pbh, *Pbl;
    cudaGetSymbolAddress((void**)&xh,  g_xh);
    cudaGetSymbolAddress((void**)&xl,  g_xl);
    cudaGetSymbolAddress((void**)&Rh,  g_Rh);
    cudaGetSymbolAddress((void**)&Rl,  g_Rl);
    cudaGetSymbolAddress((void**)&Wsh, g_Wsh);
    cudaGetSymbolAddress((void**)&Wsl, g_Wsl);
    cudaGetSymbolAddress((void**)&vh,  g_vh);
    cudaGetSymbolAddress((void**)&vl,  g_vl);
    cudaGetSymbolAddress((void**)&Qbh, g_Qbh);
    cudaGetSymbolAddress((void**)&Qbl, g_Qbl);
    cudaGetSymbolAddress((void**)&Kbh, g_Kbh);
    cudaGetSymbolAddress((void**)&Kbl, g_Kbl);
    cudaGetSymbolAddress((void**)&Vbh, g_Vbh);
    cudaGetSymbolAddress((void**)&Vbl, g_Vbl);
    cudaGetSymbolAddress((void**)&Pbh, g_Pbh);
    cudaGetSymbolAddress((void**)&Pbl, g_Pbl);

    const float* R = relpos + (size_t)1 * D;   // rows [1, 2048)

    // --- splits ---
    split_kernel<<<(BS * D + 255) / 256, 256>>>(x, xh, xl, BS * D);
    SplitBatch sw;
    sw.src[0] = Wq; sw.src[1] = Wk; sw.src[2] = Wv; sw.src[3] = Wr; sw.src[4] = Wo;
    splitW_kernel<<<dim3(D * D / 256, 5), 256>>>(sw, Wsh, Wsl);
    split_kernel<<<(LP * D + 255) / 256, 256>>>(R, Rh, Rl, LP * D);

    cudaFuncSetAttribute(gemm_tc, cudaFuncAttributeMaxDynamicSharedMemorySize,
                         GEMM_SMEM);

    // --- Q/K/V/KR + P/PR projections (merged, grid.z = 6) ---
    GemmBatch b1 = {};
    b1.Wh[0] = Wsh + 0 * (size_t)D * D; b1.Wl[0] = Wsl + 0 * (size_t)D * D;
    b1.bias[0] = bq; b1.mode[0] = 1; b1.Ch[0] = Qbh; b1.Cl[0] = Qbl;
    b1.Wh[1] = Wsh + 1 * (size_t)D * D; b1.Wl[1] = Wsl + 1 * (size_t)D * D;
    b1.bias[1] = bk; b1.mode[1] = 1; b1.Ch[1] = Kbh; b1.Cl[1] = Kbl;
    b1.Wh[2] = Wsh + 2 * (size_t)D * D; b1.Wl[2] = Wsl + 2 * (size_t)D * D;
    b1.bias[2] = bv; b1.mode[2] = 1; b1.Ch[2] = Vbh; b1.Cl[2] = Vbl;
    b1.Wh[3] = Wsh + 3 * (size_t)D * D; b1.Wl[3] = Wsl + 3 * (size_t)D * D;
    b1.bias[3] = br; b1.mode[3] = 0; b1.C[3] = KRb;
    b1.Wh[4] = Wsh + 1 * (size_t)D * D; b1.Wl[4] = Wsl + 1 * (size_t)D * D;
    b1.bias[4] = bk; b1.mode[4] = 1; b1.Ch[4] = Pbh; b1.Cl[4] = Pbl;
    b1.Wh[5] = Wsh + 3 * (size_t)D * D; b1.Wl[5] = Wsl + 3 * (size_t)D * D;
    b1.bias[5] = br; b1.mode[5] = 0; b1.C[5] = PRb;
    gemm_tc<<<dim3(8, 32, 6), 256, GEMM_SMEM>>>(xh, xl, Rh, Rl, b1, BS, LP);

    ubias_kernel<<<(B * H * S + 255) / 256, 256>>>(KRb, rel_u, ubb);
    bv_kernel<<<(H * LP + 255) / 256, 256>>>(PRb, rel_v, bvb);

    // --- tensorized attention (heavy tiles first) ---
    cudaFuncSetAttribute(attn_mma, cudaFuncAttributeMaxDynamicSharedMemorySize,
                         ATTN_SMEM_BYTES);
    attn_mma<<<dim3(B * H, S / 64), 128, ATTN_SMEM_BYTES>>>(
        Qbh, Qbl, Kbh, Kbl, Vbh, Vbl, Pbh, Pbl, ubb, bvb, vh, vl);

    // --- output projection (fp32 out) ---
    GemmBatch b3 = {};
    b3.Wh[0] = Wsh + 4 * (size_t)D * D; b3.Wl[0] = Wsl + 4 * (size_t)D * D;
    b3.bias[0] = bo; b3.mode[0] = 0; b3.C[0] = out;
    gemm_tc<<<dim3(8, 32, 1), 256, GEMM_SMEM>>>(vh, vl, nullptr, nullptr, b3, BS, BS);
}